// round 8
// baseline (speedup 1.0000x reference)
#include <cuda_runtime.h>
#include <cuda_bf16.h>
#include <math.h>
#include <stdint.h>

// Problem dims
#define BB 256
#define LL 128
#define DD 1024
#define HH 512
#define G4H 2048
#define GNF 4096
#define KS 3072
#define MM_TOT (LL * BB)
#define NBLK 128

// ---------------- scratch (device globals) ----------------------------------
__device__ float g_G[(size_t)MM_TOT * GNF];
__device__ float g_outd[2][(size_t)BB * LL * HH];
__device__ float g_h[2][2][(size_t)BB * HH];
__device__ float g_c[2][2][(size_t)BB * HH];
__device__ __nv_bfloat16 g_hhi[2][2][(size_t)BB * HH];
__device__ __nv_bfloat16 g_hlo[2][2][(size_t)BB * HH];
__device__ __nv_bfloat16 g_Xs[(size_t)MM_TOT * KS];
__device__ __nv_bfloat16 g_Ws[(size_t)GNF * KS];
__device__ __nv_bfloat16 g_Whh[2][(size_t)G4H * 1024];
__device__ float g_bias[GNF];
__device__ unsigned int g_bar_cnt;
__device__ unsigned int g_bar_gen;

// ---------------- helpers ----------------------------------------------------
__device__ __forceinline__ uint32_t smem_u32(const void* p) {
    uint32_t a;
    asm("{ .reg .u64 t; cvta.to.shared.u64 t, %1; cvt.u32.u64 %0, t; }"
        : "=r"(a) : "l"(p));
    return a;
}
#define CPA16(dst, src) \
    asm volatile("cp.async.ca.shared.global [%0], [%1], 16;" :: "r"(dst), "l"(src))
#define CPA_COMMIT() asm volatile("cp.async.commit_group;" ::: "memory")

__device__ __forceinline__ void ldmatrix_x4(uint32_t* r, uint32_t addr) {
    asm volatile("ldmatrix.sync.aligned.m8n8.x4.shared.b16 {%0,%1,%2,%3}, [%4];"
                 : "=r"(r[0]), "=r"(r[1]), "=r"(r[2]), "=r"(r[3]) : "r"(addr));
}
__device__ __forceinline__ void mma16816(float* c, const uint32_t* a,
                                         uint32_t b0, uint32_t b1) {
    asm volatile(
        "mma.sync.aligned.m16n8k16.row.col.f32.bf16.bf16.f32 "
        "{%0,%1,%2,%3}, {%4,%5,%6,%7}, {%8,%9}, {%0,%1,%2,%3};"
        : "+f"(c[0]), "+f"(c[1]), "+f"(c[2]), "+f"(c[3])
        : "r"(a[0]), "r"(a[1]), "r"(a[2]), "r"(a[3]), "r"(b0), "r"(b1));
}
__device__ __forceinline__ float fsigmoid(float x) {
    return __fdividef(1.f, 1.f + __expf(-x));
}
__device__ __forceinline__ float ftanh(float x) {
    float e2 = __expf(2.f * x);
    return __fdividef(e2 - 1.f, e2 + 1.f);
}

__device__ __forceinline__ void grid_barrier(int step) {
    __syncthreads();
    if (threadIdx.x == 0) {
        __threadfence();
        unsigned int a = atomicAdd(&g_bar_cnt, 1u);
        if (a == NBLK - 1) {
            g_bar_cnt = 0;
            __threadfence();
            atomicExch(&g_bar_gen, (unsigned)(step + 1));
        } else {
            unsigned int g;
            do {
                asm volatile("ld.acquire.gpu.u32 %0, [%1];"
                             : "=r"(g) : "l"(&g_bar_gen));
                if (g > (unsigned)step) break;
                __nanosleep(64);
            } while (true);
        }
    }
    __syncthreads();
}

// ---------------- init -------------------------------------------------------
__global__ void init_hc_kernel() {
    int i = blockIdx.x * blockDim.x + threadIdx.x;
    if (i == 0) { g_bar_cnt = 0; g_bar_gen = 0; }
    if (i < BB * HH) {
        g_h[0][0][i] = 0.f; g_h[1][0][i] = 0.f;
        g_c[0][0][i] = 0.f; g_c[1][0][i] = 0.f;
        g_hhi[0][0][i] = __float2bfloat16_rn(0.f);
        g_hhi[1][0][i] = __float2bfloat16_rn(0.f);
        g_hlo[0][0][i] = __float2bfloat16_rn(0.f);
        g_hlo[1][0][i] = __float2bfloat16_rn(0.f);
    }
}

// ---------------- fp32 -> bf16 hi/lo split converters ------------------------
__global__ __launch_bounds__(256)
void convert_x_kernel(const float* __restrict__ X) {
    const int bt = blockIdx.x;
    const int b = bt >> 7;
    const int t = bt & 127;
    const float4 v = ((const float4*)(X + (size_t)bt * DD))[threadIdx.x];
    __nv_bfloat16 hi4[4], lo4[4];
    hi4[0] = __float2bfloat16_rn(v.x); lo4[0] = __float2bfloat16_rn(v.x - __bfloat162float(hi4[0]));
    hi4[1] = __float2bfloat16_rn(v.y); lo4[1] = __float2bfloat16_rn(v.y - __bfloat162float(hi4[1]));
    hi4[2] = __float2bfloat16_rn(v.z); lo4[2] = __float2bfloat16_rn(v.z - __bfloat162float(hi4[2]));
    hi4[3] = __float2bfloat16_rn(v.w); lo4[3] = __float2bfloat16_rn(v.w - __bfloat162float(hi4[3]));
    const size_t base = ((size_t)t * BB + b) * KS + threadIdx.x * 4;
    *(uint2*)&g_Xs[base]        = *(const uint2*)hi4;
    *(uint2*)&g_Xs[base + DD]   = *(const uint2*)lo4;
    *(uint2*)&g_Xs[base + 2*DD] = *(const uint2*)hi4;
}

__global__ __launch_bounds__(256)
void convert_w_kernel(const float* __restrict__ Wf, const float* __restrict__ Wb,
                      const float* __restrict__ bf, const float* __restrict__ bb) {
    const int c = blockIdx.x;
    const int dir = (c >= G4H);
    const int local = c - dir * G4H;
    const int j = local >> 2, gate = local & 3;
    const int srow = gate * HH + j;
    const float* src = dir ? (Wb + (size_t)srow * DD) : (Wf + (size_t)srow * DD);
    const float4 v = ((const float4*)src)[threadIdx.x];
    __nv_bfloat16 hi4[4], lo4[4];
    hi4[0] = __float2bfloat16_rn(v.x); lo4[0] = __float2bfloat16_rn(v.x - __bfloat162float(hi4[0]));
    hi4[1] = __float2bfloat16_rn(v.y); lo4[1] = __float2bfloat16_rn(v.y - __bfloat162float(hi4[1]));
    hi4[2] = __float2bfloat16_rn(v.z); lo4[2] = __float2bfloat16_rn(v.z - __bfloat162float(hi4[2]));
    hi4[3] = __float2bfloat16_rn(v.w); lo4[3] = __float2bfloat16_rn(v.w - __bfloat162float(hi4[3]));
    const size_t base = (size_t)c * KS + threadIdx.x * 4;
    *(uint2*)&g_Ws[base]        = *(const uint2*)hi4;
    *(uint2*)&g_Ws[base + DD]   = *(const uint2*)hi4;
    *(uint2*)&g_Ws[base + 2*DD] = *(const uint2*)lo4;
    if (threadIdx.x == 0)
        g_bias[c] = dir ? bb[srow] : bf[srow];
}

__global__ __launch_bounds__(128)
void convert_whh_kernel(const float* __restrict__ Wf, const float* __restrict__ Wb) {
    const int c   = blockIdx.x;
    const int dir = blockIdx.y;
    const int gate = c & 3, j = c >> 2;
    const float* __restrict__ W = dir ? Wb : Wf;
    const float4 v = ((const float4*)(W + (size_t)(gate * HH + j) * HH))[threadIdx.x];
    __nv_bfloat16 hi4[4], lo4[4];
    hi4[0] = __float2bfloat16_rn(v.x); lo4[0] = __float2bfloat16_rn(v.x - __bfloat162float(hi4[0]));
    hi4[1] = __float2bfloat16_rn(v.y); lo4[1] = __float2bfloat16_rn(v.y - __bfloat162float(hi4[1]));
    hi4[2] = __float2bfloat16_rn(v.z); lo4[2] = __float2bfloat16_rn(v.z - __bfloat162float(hi4[2]));
    hi4[3] = __float2bfloat16_rn(v.w); lo4[3] = __float2bfloat16_rn(v.w - __bfloat162float(hi4[3]));
    __nv_bfloat16* dst = &g_Whh[dir][(size_t)c * 1024];
    *(uint2*)&dst[threadIdx.x * 4]       = *(const uint2*)hi4;
    *(uint2*)&dst[512 + threadIdx.x * 4] = *(const uint2*)lo4;
}

// ---------------- mma.sync input-projection GEMM (validated) -----------------
#define NKT (KS / 32)
#define SROW 80
#define STILE (128 * SROW)

__global__ __launch_bounds__(256, 2)
void gemm_mma_kernel() {
    __shared__ __align__(16) char smA[2][STILE];
    __shared__ __align__(16) char smB[2][STILE];

    const int tid  = threadIdx.x;
    const int wid  = tid >> 5;
    const int lane = tid & 31;
    const int nTile = blockIdx.x * 128;
    const int mTile = blockIdx.y * 128;

    const int wm = wid & 3;
    const int wn = wid >> 2;
    const int m0 = wm * 32;
    const int n0 = wn * 64;

    const int lrow = tid >> 1;
    const int lk   = tid & 1;
    const __nv_bfloat16* __restrict__ gA =
        g_Xs + (size_t)(mTile + lrow) * KS + lk * 16;
    const __nv_bfloat16* __restrict__ gB =
        g_Ws + (size_t)(nTile + lrow) * KS + lk * 16;

    const uint32_t baseA = smem_u32(smA);
    const uint32_t baseB = smem_u32(smB);
    const uint32_t stDstA = baseA + lrow * SROW + lk * 32;
    const uint32_t stDstB = baseB + lrow * SROW + lk * 32;

    float acc[2][8][4];
#pragma unroll
    for (int i = 0; i < 2; i++)
#pragma unroll
        for (int j = 0; j < 8; j++)
#pragma unroll
            for (int q = 0; q < 4; q++) acc[i][j][q] = 0.f;

    const int r8 = lane & 7;
    const int tI = lane >> 3;
    const uint32_t aLaneOff = (uint32_t)((r8 + (tI & 1) * 8) * SROW + (tI >> 1) * 16);
    const uint32_t bLaneOff = (uint32_t)((r8 + (tI >> 1) * 8) * SROW + (tI & 1) * 16);

    CPA16(stDstA, gA);        CPA16(stDstA + 16, gA + 8);
    CPA16(stDstB, gB);        CPA16(stDstB + 16, gB + 8);
    CPA_COMMIT();

    int buf = 0;
    for (int kt = 0; kt < NKT; kt++) {
        if (kt < NKT - 1) {
            const __nv_bfloat16* pa = gA + (size_t)(kt + 1) * 32;
            const __nv_bfloat16* pb = gB + (size_t)(kt + 1) * 32;
            const uint32_t dA = stDstA + (buf ^ 1) * STILE;
            const uint32_t dB = stDstB + (buf ^ 1) * STILE;
            CPA16(dA, pa); CPA16(dA + 16, pa + 8);
            CPA16(dB, pb); CPA16(dB + 16, pb + 8);
            CPA_COMMIT();
            asm volatile("cp.async.wait_group 1;" ::: "memory");
        } else {
            asm volatile("cp.async.wait_group 0;" ::: "memory");
        }
        __syncthreads();

        const uint32_t abuf = baseA + buf * STILE;
        const uint32_t bbuf = baseB + buf * STILE;
#pragma unroll
        for (int kk = 0; kk < 2; kk++) {
            uint32_t afr[2][4], bfr[4][4];
#pragma unroll
            for (int mi = 0; mi < 2; mi++)
                ldmatrix_x4(afr[mi],
                            abuf + (uint32_t)((m0 + mi * 16) * SROW + kk * 32) + aLaneOff);
#pragma unroll
            for (int nb = 0; nb < 4; nb++)
                ldmatrix_x4(bfr[nb],
                            bbuf + (uint32_t)((n0 + nb * 16) * SROW + kk * 32) + bLaneOff);
#pragma unroll
            for (int mi = 0; mi < 2; mi++)
#pragma unroll
                for (int ni = 0; ni < 8; ni++) {
                    const uint32_t* bp = &bfr[ni >> 1][(ni & 1) * 2];
                    mma16816(acc[mi][ni], afr[mi], bp[0], bp[1]);
                }
        }
        __syncthreads();
        buf ^= 1;
    }

    const int gid = lane >> 2;
    const int tig = lane & 3;
#pragma unroll
    for (int mi = 0; mi < 2; mi++) {
        const int m = mTile + m0 + mi * 16 + gid;
#pragma unroll
        for (int ni = 0; ni < 8; ni++) {
            const int n = nTile + n0 + ni * 8 + tig * 2;
            const float2 bv = *(const float2*)&g_bias[n];
            float2 o0 = make_float2(acc[mi][ni][0] + bv.x, acc[mi][ni][1] + bv.y);
            float2 o1 = make_float2(acc[mi][ni][2] + bv.x, acc[mi][ni][3] + bv.y);
            *(float2*)&g_G[(size_t)m * GNF + n]       = o0;
            *(float2*)&g_G[(size_t)(m + 8) * GNF + n] = o1;
        }
    }
}

// ---------------- persistent recurrence: Whi resident in SMEM ----------------
// 512 threads, 16 warps (4m x 4n), warp tile 16x32, grid (16,4,2)=128 blocks.
// SMEM: [0,133120) Whi resident (128 rows x 1040B)
//       [133120, +3*9216)  A stages (64 rows x 144B)
//       [160768, +3*18432) Wlo stages (128 rows x 144B)   total 216064
#define WROW 1040
#define WRES (128 * WROW)          // 133120
#define SROW2 144
#define A2_TILE (64 * SROW2)       // 9216
#define AOFF WRES
#define WLO_TILE (128 * SROW2)     // 18432
#define LOFF (WRES + 3 * A2_TILE)  // 160768
#define R8_SMEM (LOFF + 3 * WLO_TILE)  // 216064
#define RKT2 24

__global__ __launch_bounds__(512)
void lstm_persistent(const int* __restrict__ x_len)
{
    extern __shared__ __align__(16) char sm[];
    const uint32_t sbase = smem_u32(sm);
    float* __restrict__ sR = (float*)(sm + AOFF);

    const int tid  = threadIdx.x;
    const int wid  = tid >> 5;
    const int lane = tid & 31;
    const int nTile = blockIdx.x * 128;
    const int b0    = blockIdx.y * 64;
    const int dir   = blockIdx.z;

    const __nv_bfloat16* __restrict__ Wd = g_Whh[dir];
    float* __restrict__ outp = g_outd[dir];

    // ---- resident Whi load: 8192 x 16B chunks ----
    {
#pragma unroll
        for (int q = 0; q < 16; q++) {
            const int chunk = tid + q * 512;
            const int row = chunk >> 6;
            const int c16 = chunk & 63;
            CPA16(sbase + (uint32_t)(row * WROW + c16 * 16),
                  Wd + (size_t)(nTile + row) * 1024 + c16 * 8);
        }
        CPA_COMMIT();
        asm volatile("cp.async.wait_group 0;" ::: "memory");
        __syncthreads();
    }

    // step-invariant mappings
    const int aRow = tid >> 3;             // 0..63
    const int aC8  = (tid & 7);            // 16B chunk in row
    const uint32_t dA_off = (uint32_t)(aRow * SROW2 + aC8 * 16);

    const int m0 = (wid & 3) * 16;
    const int n0 = (wid >> 2) * 32;
    const int r8 = lane & 7;
    const int tI = lane >> 3;
    const uint32_t aLaneOff  = (uint32_t)((r8 + (tI & 1) * 8) * SROW2 + (tI >> 1) * 16);
    const uint32_t bResLane  = (uint32_t)((r8 + (tI >> 1) * 8) * WROW  + (tI & 1) * 16);
    const uint32_t bStrLane  = (uint32_t)((r8 + (tI >> 1) * 8) * SROW2 + (tI & 1) * 16);
    const int gid = lane >> 2;
    const int tig = lane & 3;
    const int jBase = nTile >> 2;

    for (int t = 0; t < LL; t++) {
        const int p = t & 1;
        const __nv_bfloat16* __restrict__ hhi = g_hhi[dir][p];
        const __nv_bfloat16* __restrict__ hlo = g_hlo[dir][p];
        const float* __restrict__ hprev = g_h[dir][p];
        const float* __restrict__ cprev = g_c[dir][p];
        float* __restrict__ hnext = g_h[dir][p ^ 1];
        float* __restrict__ cnext = g_c[dir][p ^ 1];
        __nv_bfloat16* __restrict__ hhin = g_hhi[dir][p ^ 1];
        __nv_bfloat16* __restrict__ hlon = g_hlo[dir][p ^ 1];

        auto issue_stage = [&](int kt) {
            const int stage = kt % 3;
            const int seg  = kt >> 3;
            const int ktk  = kt & 7;
            const int acol = ktk * 64;
            const __nv_bfloat16* __restrict__ hsrc = (seg == 1) ? hlo : hhi;
            // A: 512 chunks, 1 per thread
            CPA16(sbase + AOFF + stage * A2_TILE + dA_off,
                  hsrc + (size_t)(b0 + aRow) * HH + acol + aC8 * 8);
            if (seg == 2) {
                // Wlo: 1024 chunks, 2 per thread
#pragma unroll
                for (int q = 0; q < 2; q++) {
                    const int chunk = tid + q * 512;
                    const int br = chunk >> 3;
                    const int bc8 = chunk & 7;
                    CPA16(sbase + LOFF + (uint32_t)(stage * WLO_TILE + br * SROW2 + bc8 * 16),
                          Wd + (size_t)(nTile + br) * 1024 + 512 + ktk * 64 + bc8 * 8);
                }
            }
        };

        float acc[4][4];
#pragma unroll
        for (int j = 0; j < 4; j++)
#pragma unroll
            for (int q = 0; q < 4; q++) acc[j][q] = 0.f;

        issue_stage(0); CPA_COMMIT();
        issue_stage(1); CPA_COMMIT();

        for (int kt = 0; kt < RKT2; kt++) {
            if (kt + 2 < RKT2) issue_stage(kt + 2);
            CPA_COMMIT();
            asm volatile("cp.async.wait_group 2;" ::: "memory");
            __syncthreads();

            const int seg = kt >> 3;
            const int ktk = kt & 7;
            const uint32_t sa = sbase + AOFF + (kt % 3) * A2_TILE;

            if (seg < 2) {
                const uint32_t bbase = sbase + (uint32_t)(ktk * 128);
#pragma unroll
                for (int kk = 0; kk < 4; kk++) {
                    uint32_t afr[4], bfr[2][4];
                    ldmatrix_x4(afr, sa + (uint32_t)(m0 * SROW2 + kk * 32) + aLaneOff);
#pragma unroll
                    for (int nb = 0; nb < 2; nb++)
                        ldmatrix_x4(bfr[nb],
                                    bbase + (uint32_t)((n0 + nb * 16) * WROW + kk * 32) + bResLane);
#pragma unroll
                    for (int ni = 0; ni < 4; ni++) {
                        const uint32_t* bp = &bfr[ni >> 1][(ni & 1) * 2];
                        mma16816(acc[ni], afr, bp[0], bp[1]);
                    }
                }
            } else {
                const uint32_t sb = sbase + LOFF + (kt % 3) * WLO_TILE;
#pragma unroll
                for (int kk = 0; kk < 4; kk++) {
                    uint32_t afr[4], bfr[2][4];
                    ldmatrix_x4(afr, sa + (uint32_t)(m0 * SROW2 + kk * 32) + aLaneOff);
#pragma unroll
                    for (int nb = 0; nb < 2; nb++)
                        ldmatrix_x4(bfr[nb],
                                    sb + (uint32_t)((n0 + nb * 16) * SROW2 + kk * 32) + bStrLane);
#pragma unroll
                    for (int ni = 0; ni < 4; ni++) {
                        const uint32_t* bp = &bfr[ni >> 1][(ni & 1) * 2];
                        mma16816(acc[ni], afr, bp[0], bp[1]);
                    }
                }
            }
            __syncthreads();
        }

        // stage R through smem (overlays A/Wlo stage area)
#pragma unroll
        for (int ni = 0; ni < 4; ni++) {
            const int col = n0 + ni * 8 + tig * 2;
            const int row = m0 + gid;
            sR[row * 132 + col]           = acc[ni][0];
            sR[row * 132 + col + 1]       = acc[ni][1];
            sR[(row + 8) * 132 + col]     = acc[ni][2];
            sR[(row + 8) * 132 + col + 1] = acc[ni][3];
        }
        __syncthreads();

        // fused LSTM pointwise: 2048 elems / 512 threads = 4 each
#pragma unroll
        for (int it = 0; it < 4; it++) {
            const int idx = it * 512 + tid;
            const int bl = idx >> 5;
            const int jj = idx & 31;
            const int b  = b0 + bl;
            const int j  = jBase + jj;
            const int len = x_len[b];
            int tq = t;
            if (dir) { tq = len - 1 - t; if (tq < 0) tq = 0; }
            const float4 gp = *(const float4*)(
                g_G + ((size_t)tq * BB + b) * GNF + dir * G4H + (size_t)j * 4);
            const float4 rv = *(const float4*)&sR[bl * 132 + jj * 4];
            float i_ = fsigmoid(rv.x + gp.x);
            float f_ = fsigmoid(rv.y + gp.y);
            float g_ = ftanh(rv.z + gp.z);
            float o_ = fsigmoid(rv.w + gp.w);
            const size_t hc = (size_t)b * HH + j;
            float cp = cprev[hc];
            float hp = hprev[hc];
            float cn = f_ * cp + i_ * g_;
            float hn = o_ * ftanh(cn);
            const bool valid = (t < len);
            const float ho = valid ? hn : hp;
            const float co = valid ? cn : cp;
            hnext[hc] = ho;
            cnext[hc] = co;
            __nv_bfloat16 hi = __float2bfloat16_rn(ho);
            hhin[hc] = hi;
            hlon[hc] = __float2bfloat16_rn(ho - __bfloat162float(hi));
            outp[((size_t)b * LL + t) * HH + j] = valid ? hn : 0.f;
        }

        grid_barrier(t);
    }
}

// ---------------- attention + head ------------------------------------------
__global__ __launch_bounds__(256)
void final_kernel(const float* __restrict__ x, const int* __restrict__ x_len,
                  const float* __restrict__ target_word,
                  const float* __restrict__ W_h, const float* __restrict__ b_tanh,
                  const float* __restrict__ W_lin, const float* __restrict__ b_lin,
                  const float* __restrict__ W_out, const float* __restrict__ b_out,
                  float* __restrict__ out)
{
    __shared__ float s_u[LL];
    __shared__ float s_ctx[2 * HH];
    __shared__ float s_lin[512];
    __shared__ float s_red[8];
    __shared__ float s_twdot;

    const int b    = blockIdx.x;
    const int tid  = threadIdx.x;
    const int warp = tid >> 5;
    const int lane = tid & 31;
    const int len  = x_len[b];

    {
        float partial = 0.f;
        for (int d = tid; d < DD; d += 256) {
            float s = 0.f;
#pragma unroll
            for (int k = 0; k < 5; k++)
                s += target_word[((size_t)b * 5 + k) * DD + d];
            partial = fmaf(s * 0.2f, W_h[DD + d], partial);
        }
#pragma unroll
        for (int off = 16; off; off >>= 1)
            partial += __shfl_xor_sync(0xffffffffu, partial, off);
        if (lane == 0) s_red[warp] = partial;
        __syncthreads();
        if (tid == 0) {
            float s = 0.f;
            for (int w = 0; w < 8; w++) s += s_red[w];
            s_twdot = s;
        }
        __syncthreads();
    }
    const float twdot = s_twdot;

    for (int i = 0; i < 16; i++) {
        const int t = warp * 16 + i;
        const float* xe = x + ((size_t)b * LL + t) * DD;
        float a = 0.f;
#pragma unroll 8
        for (int q = 0; q < 32; q++) {
            int d = lane + q * 32;
            a = fmaf(xe[d], W_h[d], a);
        }
#pragma unroll
        for (int off = 16; off; off >>= 1)
            a += __shfl_xor_sync(0xffffffffu, a, off);
        if (lane == 0)
            s_u[t] = (t < len) ? (a + twdot + b_tanh[t]) : -1e6f;
    }
    __syncthreads();

    if (warp == 0) {
        float v[4];
#pragma unroll
        for (int q = 0; q < 4; q++) v[q] = s_u[lane + q * 32];
        float m = fmaxf(fmaxf(v[0], v[1]), fmaxf(v[2], v[3]));
#pragma unroll
        for (int off = 16; off; off >>= 1)
            m = fmaxf(m, __shfl_xor_sync(0xffffffffu, m, off));
        float e[4], s = 0.f;
#pragma unroll
        for (int q = 0; q < 4; q++) { e[q] = expf(v[q] - m); s += e[q]; }
#pragma unroll
        for (int off = 16; off; off >>= 1)
            s += __shfl_xor_sync(0xffffffffu, s, off);
        float inv = 1.f / s;
#pragma unroll
        for (int q = 0; q < 4; q++) s_u[lane + q * 32] = e[q] * inv;
    }
    __syncthreads();

    {
        float accj[4] = {0.f, 0.f, 0.f, 0.f};
        const float* outf = g_outd[0] + (size_t)b * LL * HH;
        const float* outb = g_outd[1] + (size_t)b * LL * HH;
        for (int t = 0; t < LL; t++) {
            const float a = s_u[t];
            int t2 = len - 1 - t;
            if (t2 < 0) t2 = 0;
#pragma unroll
            for (int q = 0; q < 4; q++) {
                const int j = tid + q * 256;
                float hv;
                if (j < HH) hv = outf[(size_t)t * HH + j];
                else        hv = outb[(size_t)t2 * HH + (j - HH)];
                accj[q] = fmaf(a, hv, accj[q]);
            }
        }
#pragma unroll
        for (int q = 0; q < 4; q++) s_ctx[tid + q * 256] = accj[q];
    }
    __syncthreads();

    for (int i = 0; i < 64; i++) {
        const int o = warp * 64 + i;
        const float* wr = W_lin + (size_t)o * (2 * HH);
        float a = 0.f;
#pragma unroll 8
        for (int q = 0; q < 32; q++) {
            int d = lane + q * 32;
            a = fmaf(s_ctx[d], wr[d], a);
        }
#pragma unroll
        for (int off = 16; off; off >>= 1)
            a += __shfl_xor_sync(0xffffffffu, a, off);
        if (lane == 0) s_lin[o] = fmaxf(a + b_lin[o], 0.f);
    }
    __syncthreads();

    if (warp == 0) {
#pragma unroll
        for (int o = 0; o < 3; o++) {
            const float* wr = W_out + (size_t)o * 512;
            float a = 0.f;
#pragma unroll
            for (int q = 0; q < 16; q++) {
                int d = lane + q * 32;
                a = fmaf(s_lin[d], wr[d], a);
            }
#pragma unroll
            for (int off = 16; off; off >>= 1)
                a += __shfl_xor_sync(0xffffffffu, a, off);
            if (lane == 0) out[b * 3 + o] = a + b_out[o];
        }
    }
}

// ---------------- launch -----------------------------------------------------
extern "C" void kernel_launch(void* const* d_in, const int* in_sizes, int n_in,
                              void* d_out, int out_size)
{
    const float* x           = (const float*)d_in[0];
    const int*   x_len       = (const int*)d_in[1];
    const float* target_word = (const float*)d_in[3];
    const float* W_ih_f      = (const float*)d_in[5];
    const float* W_hh_f      = (const float*)d_in[6];
    const float* b_f         = (const float*)d_in[7];
    const float* W_ih_b      = (const float*)d_in[8];
    const float* W_hh_b      = (const float*)d_in[9];
    const float* b_b         = (const float*)d_in[10];
    const float* W_h         = (const float*)d_in[11];
    const float* b_tanh      = (const float*)d_in[12];
    const float* W_lin       = (const float*)d_in[13];
    const float* b_lin       = (const float*)d_in[14];
    const float* W_out       = (const float*)d_in[15];
    const float* b_out       = (const float*)d_in[16];
    float* out = (float*)d_out;

    static bool attr_set = false;
    if (!attr_set) {
        cudaFuncSetAttribute(lstm_persistent,
                             cudaFuncAttributeMaxDynamicSharedMemorySize, R8_SMEM);
        attr_set = true;
    }

    init_hc_kernel<<<(BB * HH + 255) / 256, 256>>>();
    convert_x_kernel<<<BB * LL, 256>>>(x);
    convert_w_kernel<<<GNF, 256>>>(W_ih_f, W_ih_b, b_f, b_b);
    {
        dim3 wgrid(G4H, 2);
        convert_whh_kernel<<<wgrid, 128>>>(W_hh_f, W_hh_b);
    }

    dim3 ggrid(GNF / 128, MM_TOT / 128);   // (32, 256)
    gemm_mma_kernel<<<ggrid, 256>>>();

    dim3 sgrid(G4H / 128, BB / 64, 2);     // (16, 4, 2) = 128 persistent blocks
    lstm_persistent<<<sgrid, 512, R8_SMEM>>>(x_len);

    final_kernel<<<BB, 256>>>(x, x_len, target_word, W_h, b_tanh,
                              W_lin, b_lin, W_out, b_out, out);
}

// round 9
// speedup vs baseline: 1.0931x; 1.0931x over previous
#include <cuda_runtime.h>
#include <cuda_bf16.h>
#include <math.h>
#include <stdint.h>

// Problem dims
#define BB 256
#define LL 128
#define DD 1024
#define HH 512
#define G4H 2048
#define GNF 4096
#define KS 3072
#define MM_TOT (LL * BB)

// ---------------- scratch (device globals) ----------------------------------
__device__ float g_G[(size_t)MM_TOT * GNF];
__device__ float g_outd[2][(size_t)BB * LL * HH];
__device__ float g_h[2][2][(size_t)BB * HH];
__device__ float g_c[2][2][(size_t)BB * HH];
__device__ __nv_bfloat16 g_hhi[2][2][(size_t)BB * HH];
__device__ __nv_bfloat16 g_hlo[2][2][(size_t)BB * HH];
__device__ __nv_bfloat16 g_Xs[(size_t)MM_TOT * KS];
__device__ __nv_bfloat16 g_Ws[(size_t)GNF * KS];
__device__ __nv_bfloat16 g_Whh[2][(size_t)G4H * 1024];
__device__ float g_bias[GNF];

// per-group barriers: group = dir*4 + (b0/64); 32 blocks each
struct GrpBar { unsigned int cnt; unsigned int gen; unsigned int pad[62]; };
__device__ GrpBar g_bars[8];

// ---------------- helpers ----------------------------------------------------
__device__ __forceinline__ uint32_t smem_u32(const void* p) {
    uint32_t a;
    asm("{ .reg .u64 t; cvta.to.shared.u64 t, %1; cvt.u32.u64 %0, t; }"
        : "=r"(a) : "l"(p));
    return a;
}
#define CPA16(dst, src) \
    asm volatile("cp.async.ca.shared.global [%0], [%1], 16;" :: "r"(dst), "l"(src))
#define CPA_COMMIT() asm volatile("cp.async.commit_group;" ::: "memory")

__device__ __forceinline__ void ldmatrix_x4(uint32_t* r, uint32_t addr) {
    asm volatile("ldmatrix.sync.aligned.m8n8.x4.shared.b16 {%0,%1,%2,%3}, [%4];"
                 : "=r"(r[0]), "=r"(r[1]), "=r"(r[2]), "=r"(r[3]) : "r"(addr));
}
__device__ __forceinline__ void mma16816(float* c, const uint32_t* a,
                                         uint32_t b0, uint32_t b1) {
    asm volatile(
        "mma.sync.aligned.m16n8k16.row.col.f32.bf16.bf16.f32 "
        "{%0,%1,%2,%3}, {%4,%5,%6,%7}, {%8,%9}, {%0,%1,%2,%3};"
        : "+f"(c[0]), "+f"(c[1]), "+f"(c[2]), "+f"(c[3])
        : "r"(a[0]), "r"(a[1]), "r"(a[2]), "r"(a[3]), "r"(b0), "r"(b1));
}
__device__ __forceinline__ float fsigmoid(float x) {
    return __fdividef(1.f, 1.f + __expf(-x));
}
__device__ __forceinline__ float ftanh(float x) {
    float e2 = __expf(2.f * x);
    return __fdividef(e2 - 1.f, e2 + 1.f);
}

// 32-block group barrier
__device__ __forceinline__ void group_barrier(int gid, int step) {
    __syncthreads();
    if (threadIdx.x == 0) {
        __threadfence();
        unsigned int a = atomicAdd(&g_bars[gid].cnt, 1u);
        if (a == 31u) {
            g_bars[gid].cnt = 0;
            __threadfence();
            atomicExch(&g_bars[gid].gen, (unsigned)(step + 1));
        } else {
            unsigned int g;
            do {
                asm volatile("ld.acquire.gpu.u32 %0, [%1];"
                             : "=r"(g) : "l"(&g_bars[gid].gen));
                if (g > (unsigned)step) break;
                __nanosleep(32);
            } while (true);
        }
    }
    __syncthreads();
}

// ---------------- init -------------------------------------------------------
__global__ void init_hc_kernel() {
    int i = blockIdx.x * blockDim.x + threadIdx.x;
    if (i < 8) { g_bars[i].cnt = 0; g_bars[i].gen = 0; }
    if (i < BB * HH) {
        g_h[0][0][i] = 0.f; g_h[1][0][i] = 0.f;
        g_c[0][0][i] = 0.f; g_c[1][0][i] = 0.f;
        g_hhi[0][0][i] = __float2bfloat16_rn(0.f);
        g_hhi[1][0][i] = __float2bfloat16_rn(0.f);
        g_hlo[0][0][i] = __float2bfloat16_rn(0.f);
        g_hlo[1][0][i] = __float2bfloat16_rn(0.f);
    }
}

// ---------------- fp32 -> bf16 hi/lo split converters ------------------------
__global__ __launch_bounds__(256)
void convert_x_kernel(const float* __restrict__ X) {
    const int bt = blockIdx.x;
    const int b = bt >> 7;
    const int t = bt & 127;
    const float4 v = ((const float4*)(X + (size_t)bt * DD))[threadIdx.x];
    __nv_bfloat16 hi4[4], lo4[4];
    hi4[0] = __float2bfloat16_rn(v.x); lo4[0] = __float2bfloat16_rn(v.x - __bfloat162float(hi4[0]));
    hi4[1] = __float2bfloat16_rn(v.y); lo4[1] = __float2bfloat16_rn(v.y - __bfloat162float(hi4[1]));
    hi4[2] = __float2bfloat16_rn(v.z); lo4[2] = __float2bfloat16_rn(v.z - __bfloat162float(hi4[2]));
    hi4[3] = __float2bfloat16_rn(v.w); lo4[3] = __float2bfloat16_rn(v.w - __bfloat162float(hi4[3]));
    const size_t base = ((size_t)t * BB + b) * KS + threadIdx.x * 4;
    *(uint2*)&g_Xs[base]        = *(const uint2*)hi4;
    *(uint2*)&g_Xs[base + DD]   = *(const uint2*)lo4;
    *(uint2*)&g_Xs[base + 2*DD] = *(const uint2*)hi4;
}

__global__ __launch_bounds__(256)
void convert_w_kernel(const float* __restrict__ Wf, const float* __restrict__ Wb,
                      const float* __restrict__ bf, const float* __restrict__ bb) {
    const int c = blockIdx.x;
    const int dir = (c >= G4H);
    const int local = c - dir * G4H;
    const int j = local >> 2, gate = local & 3;
    const int srow = gate * HH + j;
    const float* src = dir ? (Wb + (size_t)srow * DD) : (Wf + (size_t)srow * DD);
    const float4 v = ((const float4*)src)[threadIdx.x];
    __nv_bfloat16 hi4[4], lo4[4];
    hi4[0] = __float2bfloat16_rn(v.x); lo4[0] = __float2bfloat16_rn(v.x - __bfloat162float(hi4[0]));
    hi4[1] = __float2bfloat16_rn(v.y); lo4[1] = __float2bfloat16_rn(v.y - __bfloat162float(hi4[1]));
    hi4[2] = __float2bfloat16_rn(v.z); lo4[2] = __float2bfloat16_rn(v.z - __bfloat162float(hi4[2]));
    hi4[3] = __float2bfloat16_rn(v.w); lo4[3] = __float2bfloat16_rn(v.w - __bfloat162float(hi4[3]));
    const size_t base = (size_t)c * KS + threadIdx.x * 4;
    *(uint2*)&g_Ws[base]        = *(const uint2*)hi4;
    *(uint2*)&g_Ws[base + DD]   = *(const uint2*)hi4;
    *(uint2*)&g_Ws[base + 2*DD] = *(const uint2*)lo4;
    if (threadIdx.x == 0)
        g_bias[c] = dir ? bb[srow] : bf[srow];
}

__global__ __launch_bounds__(128)
void convert_whh_kernel(const float* __restrict__ Wf, const float* __restrict__ Wb) {
    const int c   = blockIdx.x;
    const int dir = blockIdx.y;
    const int gate = c & 3, j = c >> 2;
    const float* __restrict__ W = dir ? Wb : Wf;
    const float4 v = ((const float4*)(W + (size_t)(gate * HH + j) * HH))[threadIdx.x];
    __nv_bfloat16 hi4[4], lo4[4];
    hi4[0] = __float2bfloat16_rn(v.x); lo4[0] = __float2bfloat16_rn(v.x - __bfloat162float(hi4[0]));
    hi4[1] = __float2bfloat16_rn(v.y); lo4[1] = __float2bfloat16_rn(v.y - __bfloat162float(hi4[1]));
    hi4[2] = __float2bfloat16_rn(v.z); lo4[2] = __float2bfloat16_rn(v.z - __bfloat162float(hi4[2]));
    hi4[3] = __float2bfloat16_rn(v.w); lo4[3] = __float2bfloat16_rn(v.w - __bfloat162float(hi4[3]));
    __nv_bfloat16* dst = &g_Whh[dir][(size_t)c * 1024];
    *(uint2*)&dst[threadIdx.x * 4]       = *(const uint2*)hi4;
    *(uint2*)&dst[512 + threadIdx.x * 4] = *(const uint2*)lo4;
}

// ---------------- mma.sync input-projection GEMM (validated) -----------------
#define NKT (KS / 32)
#define SROW 80
#define STILE (128 * SROW)

__global__ __launch_bounds__(256, 2)
void gemm_mma_kernel() {
    __shared__ __align__(16) char smA[2][STILE];
    __shared__ __align__(16) char smB[2][STILE];

    const int tid  = threadIdx.x;
    const int wid  = tid >> 5;
    const int lane = tid & 31;
    const int nTile = blockIdx.x * 128;
    const int mTile = blockIdx.y * 128;

    const int wm = wid & 3;
    const int wn = wid >> 2;
    const int m0 = wm * 32;
    const int n0 = wn * 64;

    const int lrow = tid >> 1;
    const int lk   = tid & 1;
    const __nv_bfloat16* __restrict__ gA =
        g_Xs + (size_t)(mTile + lrow) * KS + lk * 16;
    const __nv_bfloat16* __restrict__ gB =
        g_Ws + (size_t)(nTile + lrow) * KS + lk * 16;

    const uint32_t baseA = smem_u32(smA);
    const uint32_t baseB = smem_u32(smB);
    const uint32_t stDstA = baseA + lrow * SROW + lk * 32;
    const uint32_t stDstB = baseB + lrow * SROW + lk * 32;

    float acc[2][8][4];
#pragma unroll
    for (int i = 0; i < 2; i++)
#pragma unroll
        for (int j = 0; j < 8; j++)
#pragma unroll
            for (int q = 0; q < 4; q++) acc[i][j][q] = 0.f;

    const int r8 = lane & 7;
    const int tI = lane >> 3;
    const uint32_t aLaneOff = (uint32_t)((r8 + (tI & 1) * 8) * SROW + (tI >> 1) * 16);
    const uint32_t bLaneOff = (uint32_t)((r8 + (tI >> 1) * 8) * SROW + (tI & 1) * 16);

    CPA16(stDstA, gA);        CPA16(stDstA + 16, gA + 8);
    CPA16(stDstB, gB);        CPA16(stDstB + 16, gB + 8);
    CPA_COMMIT();

    int buf = 0;
    for (int kt = 0; kt < NKT; kt++) {
        if (kt < NKT - 1) {
            const __nv_bfloat16* pa = gA + (size_t)(kt + 1) * 32;
            const __nv_bfloat16* pb = gB + (size_t)(kt + 1) * 32;
            const uint32_t dA = stDstA + (buf ^ 1) * STILE;
            const uint32_t dB = stDstB + (buf ^ 1) * STILE;
            CPA16(dA, pa); CPA16(dA + 16, pa + 8);
            CPA16(dB, pb); CPA16(dB + 16, pb + 8);
            CPA_COMMIT();
            asm volatile("cp.async.wait_group 1;" ::: "memory");
        } else {
            asm volatile("cp.async.wait_group 0;" ::: "memory");
        }
        __syncthreads();

        const uint32_t abuf = baseA + buf * STILE;
        const uint32_t bbuf = baseB + buf * STILE;
#pragma unroll
        for (int kk = 0; kk < 2; kk++) {
            uint32_t afr[2][4], bfr[4][4];
#pragma unroll
            for (int mi = 0; mi < 2; mi++)
                ldmatrix_x4(afr[mi],
                            abuf + (uint32_t)((m0 + mi * 16) * SROW + kk * 32) + aLaneOff);
#pragma unroll
            for (int nb = 0; nb < 4; nb++)
                ldmatrix_x4(bfr[nb],
                            bbuf + (uint32_t)((n0 + nb * 16) * SROW + kk * 32) + bLaneOff);
#pragma unroll
            for (int mi = 0; mi < 2; mi++)
#pragma unroll
                for (int ni = 0; ni < 8; ni++) {
                    const uint32_t* bp = &bfr[ni >> 1][(ni & 1) * 2];
                    mma16816(acc[mi][ni], afr[mi], bp[0], bp[1]);
                }
        }
        __syncthreads();
        buf ^= 1;
    }

    const int gid = lane >> 2;
    const int tig = lane & 3;
#pragma unroll
    for (int mi = 0; mi < 2; mi++) {
        const int m = mTile + m0 + mi * 16 + gid;
#pragma unroll
        for (int ni = 0; ni < 8; ni++) {
            const int n = nTile + n0 + ni * 8 + tig * 2;
            const float2 bv = *(const float2*)&g_bias[n];
            float2 o0 = make_float2(acc[mi][ni][0] + bv.x, acc[mi][ni][1] + bv.y);
            float2 o1 = make_float2(acc[mi][ni][2] + bv.x, acc[mi][ni][3] + bv.y);
            *(float2*)&g_G[(size_t)m * GNF + n]       = o0;
            *(float2*)&g_G[(size_t)(m + 8) * GNF + n] = o1;
        }
    }
}

// ---------------- persistent recurrence, 256 blocks, 4-stage, 1 sync/kt -----
// Block tile: 64 batch x 64 gate-cols, K=1536. grid (32, 4, 2) = 256 blocks.
// 256 threads, 8 warps (4m x 2n), warp tile 16x32.
#define SROW2 144
#define ST_A (64 * SROW2)          // 9216
#define ST_B (64 * SROW2)          // 9216
#define STG  (ST_A + ST_B)         // 18432
#define NSTAGE 4
#define R9_SMEM (NSTAGE * STG)     // 73728
#define RKT2 24

__global__ __launch_bounds__(256, 2)
void lstm_persistent(const int* __restrict__ x_len)
{
    extern __shared__ __align__(16) char sm[];
    const uint32_t sbase = smem_u32(sm);
    float* __restrict__ sR = (float*)sm;

    const int tid  = threadIdx.x;
    const int wid  = tid >> 5;
    const int lane = tid & 31;
    const int nTile = blockIdx.x * 64;
    const int b0    = blockIdx.y * 64;
    const int dir   = blockIdx.z;
    const int grp   = dir * 4 + blockIdx.y;

    const __nv_bfloat16* __restrict__ Wd = g_Whh[dir];
    float* __restrict__ outp = g_outd[dir];

    // step-invariant load mapping: 512 chunks each for A and B, 2 per thread
    const int c0r = tid >> 3;              // chunk tid  -> row 0..31
    const int c1r = (tid + 256) >> 3;      // row 32..63
    const int c8  = (tid & 7);             // 16B chunk in 128B row
    const uint32_t off0 = (uint32_t)(c0r * SROW2 + c8 * 16);
    const uint32_t off1 = (uint32_t)(c1r * SROW2 + c8 * 16);

    // warp tiling: 4m x 2n, warp tile 16x32
    const int m0 = (wid & 3) * 16;
    const int n0 = (wid >> 2) * 32;
    const int r8 = lane & 7;
    const int tI = lane >> 3;
    const uint32_t aLaneOff = (uint32_t)((r8 + (tI & 1) * 8) * SROW2 + (tI >> 1) * 16);
    const uint32_t bLaneOff = (uint32_t)((r8 + (tI >> 1) * 8) * SROW2 + (tI & 1) * 16);
    const int gid = lane >> 2;
    const int tig = lane & 3;
    const int jBase = nTile >> 2;          // 16 j's per block

    for (int t = 0; t < LL; t++) {
        const int p = t & 1;
        const __nv_bfloat16* __restrict__ hhi = g_hhi[dir][p];
        const __nv_bfloat16* __restrict__ hlo = g_hlo[dir][p];
        const float* __restrict__ hprev = g_h[dir][p];
        const float* __restrict__ cprev = g_c[dir][p];
        float* __restrict__ hnext = g_h[dir][p ^ 1];
        float* __restrict__ cnext = g_c[dir][p ^ 1];
        __nv_bfloat16* __restrict__ hhin = g_hhi[dir][p ^ 1];
        __nv_bfloat16* __restrict__ hlon = g_hlo[dir][p ^ 1];

        auto issue_stage = [&](int kt) {
            const int stage = kt & 3;
            const int seg  = kt >> 3;
            const int ktk  = kt & 7;
            const int acol = ktk * 64;
            const int bcol = (seg == 2) ? (512 + ktk * 64) : (ktk * 64);
            const __nv_bfloat16* __restrict__ hsrc = (seg == 1) ? hlo : hhi;
            const uint32_t sa = sbase + stage * STG;
            const uint32_t sb = sa + ST_A;
            CPA16(sa + off0, hsrc + (size_t)(b0 + c0r) * HH + acol + c8 * 8);
            CPA16(sa + off1, hsrc + (size_t)(b0 + c1r) * HH + acol + c8 * 8);
            CPA16(sb + off0, Wd + (size_t)(nTile + c0r) * 1024 + bcol + c8 * 8);
            CPA16(sb + off1, Wd + (size_t)(nTile + c1r) * 1024 + bcol + c8 * 8);
        };

        float acc[4][4];
#pragma unroll
        for (int j = 0; j < 4; j++)
#pragma unroll
            for (int q = 0; q < 4; q++) acc[j][q] = 0.f;

        issue_stage(0); CPA_COMMIT();
        issue_stage(1); CPA_COMMIT();
        issue_stage(2); CPA_COMMIT();

        for (int kt = 0; kt < RKT2; kt++) {
            asm volatile("cp.async.wait_group 2;" ::: "memory");
            __syncthreads();

            const uint32_t sa = sbase + (kt & 3) * STG;
            const uint32_t sb = sa + ST_A;
#pragma unroll
            for (int kk = 0; kk < 4; kk++) {
                uint32_t afr[4], bfr[2][4];
                ldmatrix_x4(afr, sa + (uint32_t)(m0 * SROW2 + kk * 32) + aLaneOff);
#pragma unroll
                for (int nb = 0; nb < 2; nb++)
                    ldmatrix_x4(bfr[nb],
                                sb + (uint32_t)((n0 + nb * 16) * SROW2 + kk * 32) + bLaneOff);
#pragma unroll
                for (int ni = 0; ni < 4; ni++) {
                    const uint32_t* bp = &bfr[ni >> 1][(ni & 1) * 2];
                    mma16816(acc[ni], afr, bp[0], bp[1]);
                }
            }
            // issue next stage AFTER compute: single-sync correctness
            if (kt + 3 < RKT2) issue_stage(kt + 3);
            CPA_COMMIT();
        }
        asm volatile("cp.async.wait_group 0;" ::: "memory");
        __syncthreads();

        // stage R through smem: sR[batch][gatecol], stride 68
#pragma unroll
        for (int ni = 0; ni < 4; ni++) {
            const int col = n0 + ni * 8 + tig * 2;
            const int row = m0 + gid;
            sR[row * 68 + col]           = acc[ni][0];
            sR[row * 68 + col + 1]       = acc[ni][1];
            sR[(row + 8) * 68 + col]     = acc[ni][2];
            sR[(row + 8) * 68 + col + 1] = acc[ni][3];
        }
        __syncthreads();

        // fused LSTM pointwise: 64 batch x 16 j = 1024 float4 / 256 thr
#pragma unroll
        for (int it = 0; it < 4; it++) {
            const int idx = it * 256 + tid;
            const int bl = idx >> 4;        // 0..63
            const int jj = idx & 15;        // 0..15
            const int b  = b0 + bl;
            const int j  = jBase + jj;
            const int len = x_len[b];
            int tq = t;
            if (dir) { tq = len - 1 - t; if (tq < 0) tq = 0; }
            const float4 gp = *(const float4*)(
                g_G + ((size_t)tq * BB + b) * GNF + dir * G4H + (size_t)j * 4);
            const float4 rv = *(const float4*)&sR[bl * 68 + jj * 4];
            float i_ = fsigmoid(rv.x + gp.x);
            float f_ = fsigmoid(rv.y + gp.y);
            float g_ = ftanh(rv.z + gp.z);
            float o_ = fsigmoid(rv.w + gp.w);
            const size_t hc = (size_t)b * HH + j;
            float cp = cprev[hc];
            float hp = hprev[hc];
            float cn = f_ * cp + i_ * g_;
            float hn = o_ * ftanh(cn);
            const bool valid = (t < len);
            const float ho = valid ? hn : hp;
            const float co = valid ? cn : cp;
            hnext[hc] = ho;
            cnext[hc] = co;
            __nv_bfloat16 hi = __float2bfloat16_rn(ho);
            hhin[hc] = hi;
            hlon[hc] = __float2bfloat16_rn(ho - __bfloat162float(hi));
            outp[((size_t)b * LL + t) * HH + j] = valid ? hn : 0.f;
        }

        group_barrier(grp, t);
    }
}

// ---------------- attention + head ------------------------------------------
__global__ __launch_bounds__(256)
void final_kernel(const float* __restrict__ x, const int* __restrict__ x_len,
                  const float* __restrict__ target_word,
                  const float* __restrict__ W_h, const float* __restrict__ b_tanh,
                  const float* __restrict__ W_lin, const float* __restrict__ b_lin,
                  const float* __restrict__ W_out, const float* __restrict__ b_out,
                  float* __restrict__ out)
{
    __shared__ float s_u[LL];
    __shared__ float s_ctx[2 * HH];
    __shared__ float s_lin[512];
    __shared__ float s_red[8];
    __shared__ float s_twdot;

    const int b    = blockIdx.x;
    const int tid  = threadIdx.x;
    const int warp = tid >> 5;
    const int lane = tid & 31;
    const int len  = x_len[b];

    {
        float partial = 0.f;
        for (int d = tid; d < DD; d += 256) {
            float s = 0.f;
#pragma unroll
            for (int k = 0; k < 5; k++)
                s += target_word[((size_t)b * 5 + k) * DD + d];
            partial = fmaf(s * 0.2f, W_h[DD + d], partial);
        }
#pragma unroll
        for (int off = 16; off; off >>= 1)
            partial += __shfl_xor_sync(0xffffffffu, partial, off);
        if (lane == 0) s_red[warp] = partial;
        __syncthreads();
        if (tid == 0) {
            float s = 0.f;
            for (int w = 0; w < 8; w++) s += s_red[w];
            s_twdot = s;
        }
        __syncthreads();
    }
    const float twdot = s_twdot;

    for (int i = 0; i < 16; i++) {
        const int t = warp * 16 + i;
        const float* xe = x + ((size_t)b * LL + t) * DD;
        float a = 0.f;
#pragma unroll 8
        for (int q = 0; q < 32; q++) {
            int d = lane + q * 32;
            a = fmaf(xe[d], W_h[d], a);
        }
#pragma unroll
        for (int off = 16; off; off >>= 1)
            a += __shfl_xor_sync(0xffffffffu, a, off);
        if (lane == 0)
            s_u[t] = (t < len) ? (a + twdot + b_tanh[t]) : -1e6f;
    }
    __syncthreads();

    if (warp == 0) {
        float v[4];
#pragma unroll
        for (int q = 0; q < 4; q++) v[q] = s_u[lane + q * 32];
        float m = fmaxf(fmaxf(v[0], v[1]), fmaxf(v[2], v[3]));
#pragma unroll
        for (int off = 16; off; off >>= 1)
            m = fmaxf(m, __shfl_xor_sync(0xffffffffu, m, off));
        float e[4], s = 0.f;
#pragma unroll
        for (int q = 0; q < 4; q++) { e[q] = expf(v[q] - m); s += e[q]; }
#pragma unroll
        for (int off = 16; off; off >>= 1)
            s += __shfl_xor_sync(0xffffffffu, s, off);
        float inv = 1.f / s;
#pragma unroll
        for (int q = 0; q < 4; q++) s_u[lane + q * 32] = e[q] * inv;
    }
    __syncthreads();

    {
        float accj[4] = {0.f, 0.f, 0.f, 0.f};
        const float* outf = g_outd[0] + (size_t)b * LL * HH;
        const float* outb = g_outd[1] + (size_t)b * LL * HH;
        for (int t = 0; t < LL; t++) {
            const float a = s_u[t];
            int t2 = len - 1 - t;
            if (t2 < 0) t2 = 0;
#pragma unroll
            for (int q = 0; q < 4; q++) {
                const int j = tid + q * 256;
                float hv;
                if (j < HH) hv = outf[(size_t)t * HH + j];
                else        hv = outb[(size_t)t2 * HH + (j - HH)];
                accj[q] = fmaf(a, hv, accj[q]);
            }
        }
#pragma unroll
        for (int q = 0; q < 4; q++) s_ctx[tid + q * 256] = accj[q];
    }
    __syncthreads();

    for (int i = 0; i < 64; i++) {
        const int o = warp * 64 + i;
        const float* wr = W_lin + (size_t)o * (2 * HH);
        float a = 0.f;
#pragma unroll 8
        for (int q = 0; q < 32; q++) {
            int d = lane + q * 32;
            a = fmaf(s_ctx[d], wr[d], a);
        }
#pragma unroll
        for (int off = 16; off; off >>= 1)
            a += __shfl_xor_sync(0xffffffffu, a, off);
        if (lane == 0) s_lin[o] = fmaxf(a + b_lin[o], 0.f);
    }
    __syncthreads();

    if (warp == 0) {
#pragma unroll
        for (int o = 0; o < 3; o++) {
            const float* wr = W_out + (size_t)o * 512;
            float a = 0.f;
#pragma unroll
            for (int q = 0; q < 16; q++) {
                int d = lane + q * 32;
                a = fmaf(s_lin[d], wr[d], a);
            }
#pragma unroll
            for (int off = 16; off; off >>= 1)
                a += __shfl_xor_sync(0xffffffffu, a, off);
            if (lane == 0) out[b * 3 + o] = a + b_out[o];
        }
    }
}

// ---------------- launch -----------------------------------------------------
extern "C" void kernel_launch(void* const* d_in, const int* in_sizes, int n_in,
                              void* d_out, int out_size)
{
    const float* x           = (const float*)d_in[0];
    const int*   x_len       = (const int*)d_in[1];
    const float* target_word = (const float*)d_in[3];
    const float* W_ih_f      = (const float*)d_in[5];
    const float* W_hh_f      = (const float*)d_in[6];
    const float* b_f         = (const float*)d_in[7];
    const float* W_ih_b      = (const float*)d_in[8];
    const float* W_hh_b      = (const float*)d_in[9];
    const float* b_b         = (const float*)d_in[10];
    const float* W_h         = (const float*)d_in[11];
    const float* b_tanh      = (const float*)d_in[12];
    const float* W_lin       = (const float*)d_in[13];
    const float* b_lin       = (const float*)d_in[14];
    const float* W_out       = (const float*)d_in[15];
    const float* b_out       = (const float*)d_in[16];
    float* out = (float*)d_out;

    static bool attr_set = false;
    if (!attr_set) {
        cudaFuncSetAttribute(lstm_persistent,
                             cudaFuncAttributeMaxDynamicSharedMemorySize, R9_SMEM);
        attr_set = true;
    }

    init_hc_kernel<<<(BB * HH + 255) / 256, 256>>>();
    convert_x_kernel<<<BB * LL, 256>>>(x);
    convert_w_kernel<<<GNF, 256>>>(W_ih_f, W_ih_b, b_f, b_b);
    {
        dim3 wgrid(G4H, 2);
        convert_whh_kernel<<<wgrid, 128>>>(W_hh_f, W_hh_b);
    }

    dim3 ggrid(GNF / 128, MM_TOT / 128);   // (32, 256)
    gemm_mma_kernel<<<ggrid, 256>>>();

    dim3 sgrid(G4H / 64, BB / 64, 2);      // (32, 4, 2) = 256 persistent blocks
    lstm_persistent<<<sgrid, 256, R9_SMEM>>>(x_len);

    final_kernel<<<BB, 256>>>(x, x_len, target_word, W_h, b_tanh,
                              W_lin, b_lin, W_out, b_out, out);
}

// round 10
// speedup vs baseline: 1.1071x; 1.0128x over previous
#include <cuda_runtime.h>
#include <cuda_bf16.h>
#include <math.h>
#include <stdint.h>

// Problem dims
#define BB 256
#define LL 128
#define DD 1024
#define HH 512
#define G4H 2048
#define GNF 4096
#define KS 3072
#define MM_TOT (LL * BB)

// ---------------- scratch (device globals) ----------------------------------
__device__ float g_G[(size_t)MM_TOT * GNF];
__device__ float g_outd[2][(size_t)BB * LL * HH];
__device__ float g_h[2][2][(size_t)BB * HH];
__device__ float g_c[2][2][(size_t)BB * HH];
__device__ __nv_bfloat16 g_hhi[2][2][(size_t)BB * HH];
__device__ __nv_bfloat16 g_hlo[2][2][(size_t)BB * HH];
__device__ __nv_bfloat16 g_Xs[(size_t)MM_TOT * KS];
__device__ __nv_bfloat16 g_Ws[(size_t)GNF * KS];
__device__ __nv_bfloat16 g_Whh[2][(size_t)G4H * 1024];
__device__ float g_bias[GNF];

struct GrpBar { unsigned int cnt; unsigned int gen; unsigned int pad[62]; };
__device__ GrpBar g_bars[8];

// ---------------- helpers ----------------------------------------------------
__device__ __forceinline__ uint32_t smem_u32(const void* p) {
    uint32_t a;
    asm("{ .reg .u64 t; cvta.to.shared.u64 t, %1; cvt.u32.u64 %0, t; }"
        : "=r"(a) : "l"(p));
    return a;
}
#define CPA16(dst, src) \
    asm volatile("cp.async.ca.shared.global [%0], [%1], 16;" :: "r"(dst), "l"(src))
#define CPA_COMMIT() asm volatile("cp.async.commit_group;" ::: "memory")

__device__ __forceinline__ void ldmatrix_x4(uint32_t* r, uint32_t addr) {
    asm volatile("ldmatrix.sync.aligned.m8n8.x4.shared.b16 {%0,%1,%2,%3}, [%4];"
                 : "=r"(r[0]), "=r"(r[1]), "=r"(r[2]), "=r"(r[3]) : "r"(addr));
}
__device__ __forceinline__ void mma16816(float* c, const uint32_t* a,
                                         uint32_t b0, uint32_t b1) {
    asm volatile(
        "mma.sync.aligned.m16n8k16.row.col.f32.bf16.bf16.f32 "
        "{%0,%1,%2,%3}, {%4,%5,%6,%7}, {%8,%9}, {%0,%1,%2,%3};"
        : "+f"(c[0]), "+f"(c[1]), "+f"(c[2]), "+f"(c[3])
        : "r"(a[0]), "r"(a[1]), "r"(a[2]), "r"(a[3]), "r"(b0), "r"(b1));
}
__device__ __forceinline__ float fsigmoid(float x) {
    return __fdividef(1.f, 1.f + __expf(-x));
}
__device__ __forceinline__ float ftanh(float x) {
    float e2 = __expf(2.f * x);
    return __fdividef(e2 - 1.f, e2 + 1.f);
}

__device__ __forceinline__ void group_barrier(int gid, int step) {
    __syncthreads();
    if (threadIdx.x == 0) {
        __threadfence();
        unsigned int a = atomicAdd(&g_bars[gid].cnt, 1u);
        if (a == 31u) {
            g_bars[gid].cnt = 0;
            __threadfence();
            atomicExch(&g_bars[gid].gen, (unsigned)(step + 1));
        } else {
            unsigned int g;
            do {
                asm volatile("ld.acquire.gpu.u32 %0, [%1];"
                             : "=r"(g) : "l"(&g_bars[gid].gen));
                if (g > (unsigned)step) break;
                __nanosleep(32);
            } while (true);
        }
    }
    __syncthreads();
}

// ---------------- init -------------------------------------------------------
__global__ void init_hc_kernel() {
    int i = blockIdx.x * blockDim.x + threadIdx.x;
    if (i < 8) { g_bars[i].cnt = 0; g_bars[i].gen = 0; }
    if (i < BB * HH) {
        g_h[0][0][i] = 0.f; g_h[1][0][i] = 0.f;
        g_c[0][0][i] = 0.f; g_c[1][0][i] = 0.f;
        g_hhi[0][0][i] = __float2bfloat16_rn(0.f);
        g_hhi[1][0][i] = __float2bfloat16_rn(0.f);
        g_hlo[0][0][i] = __float2bfloat16_rn(0.f);
        g_hlo[1][0][i] = __float2bfloat16_rn(0.f);
    }
}

// ---------------- fp32 -> bf16 hi/lo split converters ------------------------
__global__ __launch_bounds__(256)
void convert_x_kernel(const float* __restrict__ X) {
    const int bt = blockIdx.x;
    const int b = bt >> 7;
    const int t = bt & 127;
    const float4 v = ((const float4*)(X + (size_t)bt * DD))[threadIdx.x];
    __nv_bfloat16 hi4[4], lo4[4];
    hi4[0] = __float2bfloat16_rn(v.x); lo4[0] = __float2bfloat16_rn(v.x - __bfloat162float(hi4[0]));
    hi4[1] = __float2bfloat16_rn(v.y); lo4[1] = __float2bfloat16_rn(v.y - __bfloat162float(hi4[1]));
    hi4[2] = __float2bfloat16_rn(v.z); lo4[2] = __float2bfloat16_rn(v.z - __bfloat162float(hi4[2]));
    hi4[3] = __float2bfloat16_rn(v.w); lo4[3] = __float2bfloat16_rn(v.w - __bfloat162float(hi4[3]));
    const size_t base = ((size_t)t * BB + b) * KS + threadIdx.x * 4;
    *(uint2*)&g_Xs[base]        = *(const uint2*)hi4;
    *(uint2*)&g_Xs[base + DD]   = *(const uint2*)lo4;
    *(uint2*)&g_Xs[base + 2*DD] = *(const uint2*)hi4;
}

__global__ __launch_bounds__(256)
void convert_w_kernel(const float* __restrict__ Wf, const float* __restrict__ Wb,
                      const float* __restrict__ bf, const float* __restrict__ bb) {
    const int c = blockIdx.x;
    const int dir = (c >= G4H);
    const int local = c - dir * G4H;
    const int j = local >> 2, gate = local & 3;
    const int srow = gate * HH + j;
    const float* src = dir ? (Wb + (size_t)srow * DD) : (Wf + (size_t)srow * DD);
    const float4 v = ((const float4*)src)[threadIdx.x];
    __nv_bfloat16 hi4[4], lo4[4];
    hi4[0] = __float2bfloat16_rn(v.x); lo4[0] = __float2bfloat16_rn(v.x - __bfloat162float(hi4[0]));
    hi4[1] = __float2bfloat16_rn(v.y); lo4[1] = __float2bfloat16_rn(v.y - __bfloat162float(hi4[1]));
    hi4[2] = __float2bfloat16_rn(v.z); lo4[2] = __float2bfloat16_rn(v.z - __bfloat162float(hi4[2]));
    hi4[3] = __float2bfloat16_rn(v.w); lo4[3] = __float2bfloat16_rn(v.w - __bfloat162float(hi4[3]));
    const size_t base = (size_t)c * KS + threadIdx.x * 4;
    *(uint2*)&g_Ws[base]        = *(const uint2*)hi4;
    *(uint2*)&g_Ws[base + DD]   = *(const uint2*)hi4;
    *(uint2*)&g_Ws[base + 2*DD] = *(const uint2*)lo4;
    if (threadIdx.x == 0)
        g_bias[c] = dir ? bb[srow] : bf[srow];
}

__global__ __launch_bounds__(128)
void convert_whh_kernel(const float* __restrict__ Wf, const float* __restrict__ Wb) {
    const int c   = blockIdx.x;
    const int dir = blockIdx.y;
    const int gate = c & 3, j = c >> 2;
    const float* __restrict__ W = dir ? Wb : Wf;
    const float4 v = ((const float4*)(W + (size_t)(gate * HH + j) * HH))[threadIdx.x];
    __nv_bfloat16 hi4[4], lo4[4];
    hi4[0] = __float2bfloat16_rn(v.x); lo4[0] = __float2bfloat16_rn(v.x - __bfloat162float(hi4[0]));
    hi4[1] = __float2bfloat16_rn(v.y); lo4[1] = __float2bfloat16_rn(v.y - __bfloat162float(hi4[1]));
    hi4[2] = __float2bfloat16_rn(v.z); lo4[2] = __float2bfloat16_rn(v.z - __bfloat162float(hi4[2]));
    hi4[3] = __float2bfloat16_rn(v.w); lo4[3] = __float2bfloat16_rn(v.w - __bfloat162float(hi4[3]));
    __nv_bfloat16* dst = &g_Whh[dir][(size_t)c * 1024];
    *(uint2*)&dst[threadIdx.x * 4]       = *(const uint2*)hi4;
    *(uint2*)&dst[512 + threadIdx.x * 4] = *(const uint2*)lo4;
}

// ---------------- mma.sync input-projection GEMM (validated) -----------------
#define NKT (KS / 32)
#define SROW 80
#define STILE (128 * SROW)

__global__ __launch_bounds__(256, 2)
void gemm_mma_kernel() {
    __shared__ __align__(16) char smA[2][STILE];
    __shared__ __align__(16) char smB[2][STILE];

    const int tid  = threadIdx.x;
    const int wid  = tid >> 5;
    const int lane = tid & 31;
    const int nTile = blockIdx.x * 128;
    const int mTile = blockIdx.y * 128;

    const int wm = wid & 3;
    const int wn = wid >> 2;
    const int m0 = wm * 32;
    const int n0 = wn * 64;

    const int lrow = tid >> 1;
    const int lk   = tid & 1;
    const __nv_bfloat16* __restrict__ gA =
        g_Xs + (size_t)(mTile + lrow) * KS + lk * 16;
    const __nv_bfloat16* __restrict__ gB =
        g_Ws + (size_t)(nTile + lrow) * KS + lk * 16;

    const uint32_t baseA = smem_u32(smA);
    const uint32_t baseB = smem_u32(smB);
    const uint32_t stDstA = baseA + lrow * SROW + lk * 32;
    const uint32_t stDstB = baseB + lrow * SROW + lk * 32;

    float acc[2][8][4];
#pragma unroll
    for (int i = 0; i < 2; i++)
#pragma unroll
        for (int j = 0; j < 8; j++)
#pragma unroll
            for (int q = 0; q < 4; q++) acc[i][j][q] = 0.f;

    const int r8 = lane & 7;
    const int tI = lane >> 3;
    const uint32_t aLaneOff = (uint32_t)((r8 + (tI & 1) * 8) * SROW + (tI >> 1) * 16);
    const uint32_t bLaneOff = (uint32_t)((r8 + (tI >> 1) * 8) * SROW + (tI & 1) * 16);

    CPA16(stDstA, gA);        CPA16(stDstA + 16, gA + 8);
    CPA16(stDstB, gB);        CPA16(stDstB + 16, gB + 8);
    CPA_COMMIT();

    int buf = 0;
    for (int kt = 0; kt < NKT; kt++) {
        if (kt < NKT - 1) {
            const __nv_bfloat16* pa = gA + (size_t)(kt + 1) * 32;
            const __nv_bfloat16* pb = gB + (size_t)(kt + 1) * 32;
            const uint32_t dA = stDstA + (buf ^ 1) * STILE;
            const uint32_t dB = stDstB + (buf ^ 1) * STILE;
            CPA16(dA, pa); CPA16(dA + 16, pa + 8);
            CPA16(dB, pb); CPA16(dB + 16, pb + 8);
            CPA_COMMIT();
            asm volatile("cp.async.wait_group 1;" ::: "memory");
        } else {
            asm volatile("cp.async.wait_group 0;" ::: "memory");
        }
        __syncthreads();

        const uint32_t abuf = baseA + buf * STILE;
        const uint32_t bbuf = baseB + buf * STILE;
#pragma unroll
        for (int kk = 0; kk < 2; kk++) {
            uint32_t afr[2][4], bfr[4][4];
#pragma unroll
            for (int mi = 0; mi < 2; mi++)
                ldmatrix_x4(afr[mi],
                            abuf + (uint32_t)((m0 + mi * 16) * SROW + kk * 32) + aLaneOff);
#pragma unroll
            for (int nb = 0; nb < 4; nb++)
                ldmatrix_x4(bfr[nb],
                            bbuf + (uint32_t)((n0 + nb * 16) * SROW + kk * 32) + bLaneOff);
#pragma unroll
            for (int mi = 0; mi < 2; mi++)
#pragma unroll
                for (int ni = 0; ni < 8; ni++) {
                    const uint32_t* bp = &bfr[ni >> 1][(ni & 1) * 2];
                    mma16816(acc[mi][ni], afr[mi], bp[0], bp[1]);
                }
        }
        __syncthreads();
        buf ^= 1;
    }

    const int gid = lane >> 2;
    const int tig = lane & 3;
#pragma unroll
    for (int mi = 0; mi < 2; mi++) {
        const int m = mTile + m0 + mi * 16 + gid;
#pragma unroll
        for (int ni = 0; ni < 8; ni++) {
            const int n = nTile + n0 + ni * 8 + tig * 2;
            const float2 bv = *(const float2*)&g_bias[n];
            float2 o0 = make_float2(acc[mi][ni][0] + bv.x, acc[mi][ni][1] + bv.y);
            float2 o1 = make_float2(acc[mi][ni][2] + bv.x, acc[mi][ni][3] + bv.y);
            *(float2*)&g_G[(size_t)m * GNF + n]       = o0;
            *(float2*)&g_G[(size_t)(m + 8) * GNF + n] = o1;
        }
    }
}

// ---------------- persistent recurrence: K-split warp groups -----------------
// Block: 64 batch x 64 gate-cols. Warps 0-3: even k-tiles, warps 4-7: odd.
// Warp tile 32x32. 12 paired iterations, 6 stages, 1 sync/pair.
#define SROW2 144
#define ST_A (64 * SROW2)          // 9216
#define ST_B (64 * SROW2)          // 9216
#define STG  (ST_A + ST_B)         // 18432
#define NST 6
#define R10_SMEM (NST * STG)       // 110592
#define RKT2 24
#define NPAIR 12
#define SRBUF (64 * 68 * 4)        // 17408 bytes per sR buffer

__global__ __launch_bounds__(256, 2)
void lstm_persistent(const int* __restrict__ x_len)
{
    extern __shared__ __align__(16) char sm[];
    const uint32_t sbase = smem_u32(sm);

    const int tid  = threadIdx.x;
    const int wid  = tid >> 5;
    const int lane = tid & 31;
    const int nTile = blockIdx.x * 64;
    const int b0    = blockIdx.y * 64;
    const int dir   = blockIdx.z;
    const int grp   = dir * 4 + blockIdx.y;

    const __nv_bfloat16* __restrict__ Wd = g_Whh[dir];
    float* __restrict__ outp = g_outd[dir];

    // k-split: warps 0-3 -> even tiles, 4-7 -> odd tiles
    const int ksg = wid >> 2;               // 0 or 1
    const int w4  = wid & 3;
    const int m0  = (w4 & 1) * 32;
    const int n0  = (w4 >> 1) * 32;

    // load mapping: per tile, 512 A chunks + 512 B chunks, 2+2 per thread
    const int c0r = tid >> 3;
    const int c1r = (tid + 256) >> 3;
    const int c8  = (tid & 7);
    const uint32_t off0 = (uint32_t)(c0r * SROW2 + c8 * 16);
    const uint32_t off1 = (uint32_t)(c1r * SROW2 + c8 * 16);

    const int r8 = lane & 7;
    const int tI = lane >> 3;
    const uint32_t aLaneOff = (uint32_t)((r8 + (tI & 1) * 8) * SROW2 + (tI >> 1) * 16);
    const uint32_t bLaneOff = (uint32_t)((r8 + (tI >> 1) * 8) * SROW2 + (tI & 1) * 16);
    const int gid = lane >> 2;
    const int tig = lane & 3;
    const int jBase = nTile >> 2;

    float* __restrict__ sR0 = (float*)sm;
    float* __restrict__ sR1 = (float*)(sm + SRBUF);
    float* __restrict__ sRme = ksg ? sR1 : sR0;

    for (int t = 0; t < LL; t++) {
        const int p2 = t & 1;
        const __nv_bfloat16* __restrict__ hhi = g_hhi[dir][p2];
        const __nv_bfloat16* __restrict__ hlo = g_hlo[dir][p2];
        const float* __restrict__ hprev = g_h[dir][p2];
        const float* __restrict__ cprev = g_c[dir][p2];
        float* __restrict__ hnext = g_h[dir][p2 ^ 1];
        float* __restrict__ cnext = g_c[dir][p2 ^ 1];
        __nv_bfloat16* __restrict__ hhin = g_hhi[dir][p2 ^ 1];
        __nv_bfloat16* __restrict__ hlon = g_hlo[dir][p2 ^ 1];

        // ---- prefetch G (independent of h) ----
        float4 gp[4];
#pragma unroll
        for (int it = 0; it < 4; it++) {
            const int idx = it * 256 + tid;
            const int bl = idx >> 4;
            const int jj = idx & 15;
            const int b  = b0 + bl;
            const int len = x_len[b];
            int tq = t;
            if (dir) { tq = len - 1 - t; if (tq < 0) tq = 0; }
            gp[it] = *(const float4*)(
                g_G + ((size_t)tq * BB + b) * GNF + dir * G4H + (size_t)(jBase + jj) * 4);
        }

        auto issue_stage = [&](int kt) {
            const int stage = kt % NST;
            const int seg  = kt >> 3;
            const int ktk  = kt & 7;
            const int acol = ktk * 64;
            const int bcol = (seg == 2) ? (512 + ktk * 64) : (ktk * 64);
            const __nv_bfloat16* __restrict__ hsrc = (seg == 1) ? hlo : hhi;
            const uint32_t sa = sbase + stage * STG;
            const uint32_t sb = sa + ST_A;
            CPA16(sa + off0, hsrc + (size_t)(b0 + c0r) * HH + acol + c8 * 8);
            CPA16(sa + off1, hsrc + (size_t)(b0 + c1r) * HH + acol + c8 * 8);
            CPA16(sb + off0, Wd + (size_t)(nTile + c0r) * 1024 + bcol + c8 * 8);
            CPA16(sb + off1, Wd + (size_t)(nTile + c1r) * 1024 + bcol + c8 * 8);
        };

        float acc[2][4][4];
#pragma unroll
        for (int i = 0; i < 2; i++)
#pragma unroll
            for (int j = 0; j < 4; j++)
#pragma unroll
                for (int q = 0; q < 4; q++) acc[i][j][q] = 0.f;

        issue_stage(0); issue_stage(1); CPA_COMMIT();
        issue_stage(2); issue_stage(3); CPA_COMMIT();

        for (int p = 0; p < NPAIR; p++) {
            asm volatile("cp.async.wait_group 1;" ::: "memory");
            __syncthreads();

            const int kt = 2 * p + ksg;
            const uint32_t sa = sbase + (kt % NST) * STG;
            const uint32_t sb = sa + ST_A;
#pragma unroll
            for (int kk = 0; kk < 4; kk++) {
                uint32_t afr[2][4], bfr[2][4];
#pragma unroll
                for (int mi = 0; mi < 2; mi++)
                    ldmatrix_x4(afr[mi],
                                sa + (uint32_t)((m0 + mi * 16) * SROW2 + kk * 32) + aLaneOff);
#pragma unroll
                for (int nb = 0; nb < 2; nb++)
                    ldmatrix_x4(bfr[nb],
                                sb + (uint32_t)((n0 + nb * 16) * SROW2 + kk * 32) + bLaneOff);
#pragma unroll
                for (int mi = 0; mi < 2; mi++)
#pragma unroll
                    for (int ni = 0; ni < 4; ni++) {
                        const uint32_t* bp = &bfr[ni >> 1][(ni & 1) * 2];
                        mma16816(acc[mi][ni], afr[mi], bp[0], bp[1]);
                    }
            }
            if (p + 2 < NPAIR) { issue_stage(2 * p + 4); issue_stage(2 * p + 5); }
            CPA_COMMIT();
        }
        asm volatile("cp.async.wait_group 0;" ::: "memory");
        __syncthreads();

        // ---- each k-split group writes its partial R ----
#pragma unroll
        for (int mi = 0; mi < 2; mi++) {
            const int row = m0 + mi * 16 + gid;
#pragma unroll
            for (int ni = 0; ni < 4; ni++) {
                const int col = n0 + ni * 8 + tig * 2;
                sRme[row * 68 + col]           = acc[mi][ni][0];
                sRme[row * 68 + col + 1]       = acc[mi][ni][1];
                sRme[(row + 8) * 68 + col]     = acc[mi][ni][2];
                sRme[(row + 8) * 68 + col + 1] = acc[mi][ni][3];
            }
        }
        __syncthreads();

        // ---- fused LSTM pointwise (R = sR0 + sR1, G prefetched) ----
#pragma unroll
        for (int it = 0; it < 4; it++) {
            const int idx = it * 256 + tid;
            const int bl = idx >> 4;
            const int jj = idx & 15;
            const int b  = b0 + bl;
            const int j  = jBase + jj;
            const int len = x_len[b];
            const float4 r0 = *(const float4*)&sR0[bl * 68 + jj * 4];
            const float4 r1 = *(const float4*)&sR1[bl * 68 + jj * 4];
            float i_ = fsigmoid(r0.x + r1.x + gp[it].x);
            float f_ = fsigmoid(r0.y + r1.y + gp[it].y);
            float g_ = ftanh(r0.z + r1.z + gp[it].z);
            float o_ = fsigmoid(r0.w + r1.w + gp[it].w);
            const size_t hc = (size_t)b * HH + j;
            float cp = cprev[hc];
            float hp = hprev[hc];
            float cn = f_ * cp + i_ * g_;
            float hn = o_ * ftanh(cn);
            const bool valid = (t < len);
            const float ho = valid ? hn : hp;
            const float co = valid ? cn : cp;
            hnext[hc] = ho;
            cnext[hc] = co;
            __nv_bfloat16 hi = __float2bfloat16_rn(ho);
            hhin[hc] = hi;
            hlon[hc] = __float2bfloat16_rn(ho - __bfloat162float(hi));
            outp[((size_t)b * LL + t) * HH + j] = valid ? hn : 0.f;
        }

        group_barrier(grp, t);
    }
}

// ---------------- attention + head ------------------------------------------
__global__ __launch_bounds__(256)
void final_kernel(const float* __restrict__ x, const int* __restrict__ x_len,
                  const float* __restrict__ target_word,
                  const float* __restrict__ W_h, const float* __restrict__ b_tanh,
                  const float* __restrict__ W_lin, const float* __restrict__ b_lin,
                  const float* __restrict__ W_out, const float* __restrict__ b_out,
                  float* __restrict__ out)
{
    __shared__ float s_u[LL];
    __shared__ float s_ctx[2 * HH];
    __shared__ float s_lin[512];
    __shared__ float s_red[8];
    __shared__ float s_twdot;

    const int b    = blockIdx.x;
    const int tid  = threadIdx.x;
    const int warp = tid >> 5;
    const int lane = tid & 31;
    const int len  = x_len[b];

    {
        float partial = 0.f;
        for (int d = tid; d < DD; d += 256) {
            float s = 0.f;
#pragma unroll
            for (int k = 0; k < 5; k++)
                s += target_word[((size_t)b * 5 + k) * DD + d];
            partial = fmaf(s * 0.2f, W_h[DD + d], partial);
        }
#pragma unroll
        for (int off = 16; off; off >>= 1)
            partial += __shfl_xor_sync(0xffffffffu, partial, off);
        if (lane == 0) s_red[warp] = partial;
        __syncthreads();
        if (tid == 0) {
            float s = 0.f;
            for (int w = 0; w < 8; w++) s += s_red[w];
            s_twdot = s;
        }
        __syncthreads();
    }
    const float twdot = s_twdot;

    for (int i = 0; i < 16; i++) {
        const int t = warp * 16 + i;
        const float* xe = x + ((size_t)b * LL + t) * DD;
        float a = 0.f;
#pragma unroll 8
        for (int q = 0; q < 32; q++) {
            int d = lane + q * 32;
            a = fmaf(xe[d], W_h[d], a);
        }
#pragma unroll
        for (int off = 16; off; off >>= 1)
            a += __shfl_xor_sync(0xffffffffu, a, off);
        if (lane == 0)
            s_u[t] = (t < len) ? (a + twdot + b_tanh[t]) : -1e6f;
    }
    __syncthreads();

    if (warp == 0) {
        float v[4];
#pragma unroll
        for (int q = 0; q < 4; q++) v[q] = s_u[lane + q * 32];
        float m = fmaxf(fmaxf(v[0], v[1]), fmaxf(v[2], v[3]));
#pragma unroll
        for (int off = 16; off; off >>= 1)
            m = fmaxf(m, __shfl_xor_sync(0xffffffffu, m, off));
        float e[4], s = 0.f;
#pragma unroll
        for (int q = 0; q < 4; q++) { e[q] = expf(v[q] - m); s += e[q]; }
#pragma unroll
        for (int off = 16; off; off >>= 1)
            s += __shfl_xor_sync(0xffffffffu, s, off);
        float inv = 1.f / s;
#pragma unroll
        for (int q = 0; q < 4; q++) s_u[lane + q * 32] = e[q] * inv;
    }
    __syncthreads();

    {
        float accj[4] = {0.f, 0.f, 0.f, 0.f};
        const float* outf = g_outd[0] + (size_t)b * LL * HH;
        const float* outb = g_outd[1] + (size_t)b * LL * HH;
        for (int t = 0; t < LL; t++) {
            const float a = s_u[t];
            int t2 = len - 1 - t;
            if (t2 < 0) t2 = 0;
#pragma unroll
            for (int q = 0; q < 4; q++) {
                const int j = tid + q * 256;
                float hv;
                if (j < HH) hv = outf[(size_t)t * HH + j];
                else        hv = outb[(size_t)t2 * HH + (j - HH)];
                accj[q] = fmaf(a, hv, accj[q]);
            }
        }
#pragma unroll
        for (int q = 0; q < 4; q++) s_ctx[tid + q * 256] = accj[q];
    }
    __syncthreads();

    for (int i = 0; i < 64; i++) {
        const int o = warp * 64 + i;
        const float* wr = W_lin + (size_t)o * (2 * HH);
        float a = 0.f;
#pragma unroll 8
        for (int q = 0; q < 32; q++) {
            int d = lane + q * 32;
            a = fmaf(s_ctx[d], wr[d], a);
        }
#pragma unroll
        for (int off = 16; off; off >>= 1)
            a += __shfl_xor_sync(0xffffffffu, a, off);
        if (lane == 0) s_lin[o] = fmaxf(a + b_lin[o], 0.f);
    }
    __syncthreads();

    if (warp == 0) {
#pragma unroll
        for (int o = 0; o < 3; o++) {
            const float* wr = W_out + (size_t)o * 512;
            float a = 0.f;
#pragma unroll
            for (int q = 0; q < 16; q++) {
                int d = lane + q * 32;
                a = fmaf(s_lin[d], wr[d], a);
            }
#pragma unroll
            for (int off = 16; off; off >>= 1)
                a += __shfl_xor_sync(0xffffffffu, a, off);
            if (lane == 0) out[b * 3 + o] = a + b_out[o];
        }
    }
}

// ---------------- launch -----------------------------------------------------
extern "C" void kernel_launch(void* const* d_in, const int* in_sizes, int n_in,
                              void* d_out, int out_size)
{
    const float* x           = (const float*)d_in[0];
    const int*   x_len       = (const int*)d_in[1];
    const float* target_word = (const float*)d_in[3];
    const float* W_ih_f      = (const float*)d_in[5];
    const float* W_hh_f      = (const float*)d_in[6];
    const float* b_f         = (const float*)d_in[7];
    const float* W_ih_b      = (const float*)d_in[8];
    const float* W_hh_b      = (const float*)d_in[9];
    const float* b_b         = (const float*)d_in[10];
    const float* W_h         = (const float*)d_in[11];
    const float* b_tanh      = (const float*)d_in[12];
    const float* W_lin       = (const float*)d_in[13];
    const float* b_lin       = (const float*)d_in[14];
    const float* W_out       = (const float*)d_in[15];
    const float* b_out       = (const float*)d_in[16];
    float* out = (float*)d_out;

    static bool attr_set = false;
    if (!attr_set) {
        cudaFuncSetAttribute(lstm_persistent,
                             cudaFuncAttributeMaxDynamicSharedMemorySize, R10_SMEM);
        attr_set = true;
    }

    init_hc_kernel<<<(BB * HH + 255) / 256, 256>>>();
    convert_x_kernel<<<BB * LL, 256>>>(x);
    convert_w_kernel<<<GNF, 256>>>(W_ih_f, W_ih_b, b_f, b_b);
    {
        dim3 wgrid(G4H, 2);
        convert_whh_kernel<<<wgrid, 128>>>(W_hh_f, W_hh_b);
    }

    dim3 ggrid(GNF / 128, MM_TOT / 128);   // (32, 256)
    gemm_mma_kernel<<<ggrid, 256>>>();

    dim3 sgrid(G4H / 64, BB / 64, 2);      // (32, 4, 2) = 256 persistent blocks
    lstm_persistent<<<sgrid, 256, R10_SMEM>>>(x_len);

    final_kernel<<<BB, 256>>>(x, x_len, target_word, W_h, b_tanh,
                              W_lin, b_lin, W_out, b_out, out);
}

// round 11
// speedup vs baseline: 1.2337x; 1.1144x over previous
#include <cuda_runtime.h>
#include <cuda_bf16.h>
#include <math.h>
#include <stdint.h>

// Problem dims
#define BB 256
#define LL 128
#define DD 1024
#define HH 512
#define G4H 2048
#define GNF 4096
#define KS 3072
#define MM_TOT (LL * BB)

// ---------------- scratch (device globals) ----------------------------------
__device__ float g_G[(size_t)MM_TOT * GNF];
__device__ float g_outd[2][(size_t)BB * LL * HH];
__device__ float g_h[2][2][(size_t)BB * HH];
__device__ float g_c[2][2][(size_t)BB * HH];
__device__ __nv_bfloat16 g_hhi[2][2][(size_t)BB * HH];
__device__ __nv_bfloat16 g_hlo[2][2][(size_t)BB * HH];
__device__ __nv_bfloat16 g_Xs[(size_t)MM_TOT * KS];
__device__ __nv_bfloat16 g_Ws[(size_t)GNF * KS];
__device__ __nv_bfloat16 g_Whh[2][(size_t)G4H * 1024];
__device__ float g_bias[GNF];

struct GrpBar { unsigned int cnt; unsigned int gen; unsigned int pad[62]; };
__device__ GrpBar g_bars[8];

// ---------------- helpers ----------------------------------------------------
__device__ __forceinline__ uint32_t smem_u32(const void* p) {
    uint32_t a;
    asm("{ .reg .u64 t; cvta.to.shared.u64 t, %1; cvt.u32.u64 %0, t; }"
        : "=r"(a) : "l"(p));
    return a;
}
#define CPA16(dst, src) \
    asm volatile("cp.async.ca.shared.global [%0], [%1], 16;" :: "r"(dst), "l"(src))
#define CPA_COMMIT() asm volatile("cp.async.commit_group;" ::: "memory")

__device__ __forceinline__ void ldmatrix_x4(uint32_t* r, uint32_t addr) {
    asm volatile("ldmatrix.sync.aligned.m8n8.x4.shared.b16 {%0,%1,%2,%3}, [%4];"
                 : "=r"(r[0]), "=r"(r[1]), "=r"(r[2]), "=r"(r[3]) : "r"(addr));
}
__device__ __forceinline__ void mma16816(float* c, const uint32_t* a,
                                         uint32_t b0, uint32_t b1) {
    asm volatile(
        "mma.sync.aligned.m16n8k16.row.col.f32.bf16.bf16.f32 "
        "{%0,%1,%2,%3}, {%4,%5,%6,%7}, {%8,%9}, {%0,%1,%2,%3};"
        : "+f"(c[0]), "+f"(c[1]), "+f"(c[2]), "+f"(c[3])
        : "r"(a[0]), "r"(a[1]), "r"(a[2]), "r"(a[3]), "r"(b0), "r"(b1));
}
__device__ __forceinline__ float fsigmoid(float x) {
    return __fdividef(1.f, 1.f + __expf(-x));
}
__device__ __forceinline__ float ftanh(float x) {
    float e2 = __expf(2.f * x);
    return __fdividef(e2 - 1.f, e2 + 1.f);
}

__device__ __forceinline__ void group_barrier(int gid, int step) {
    __syncthreads();
    if (threadIdx.x == 0) {
        __threadfence();
        unsigned int a = atomicAdd(&g_bars[gid].cnt, 1u);
        if (a == 31u) {
            g_bars[gid].cnt = 0;
            __threadfence();
            atomicExch(&g_bars[gid].gen, (unsigned)(step + 1));
        } else {
            unsigned int g;
            do {
                asm volatile("ld.acquire.gpu.u32 %0, [%1];"
                             : "=r"(g) : "l"(&g_bars[gid].gen));
                if (g > (unsigned)step) break;
                __nanosleep(32);
            } while (true);
        }
    }
    __syncthreads();
}

// ---------------- init -------------------------------------------------------
__global__ void init_hc_kernel() {
    int i = blockIdx.x * blockDim.x + threadIdx.x;
    if (i < 8) { g_bars[i].cnt = 0; g_bars[i].gen = 0; }
    if (i < BB * HH) {
        g_h[0][0][i] = 0.f; g_h[1][0][i] = 0.f;
        g_c[0][0][i] = 0.f; g_c[1][0][i] = 0.f;
        g_hhi[0][0][i] = __float2bfloat16_rn(0.f);
        g_hhi[1][0][i] = __float2bfloat16_rn(0.f);
        g_hlo[0][0][i] = __float2bfloat16_rn(0.f);
        g_hlo[1][0][i] = __float2bfloat16_rn(0.f);
    }
}

// ---------------- fp32 -> bf16 hi/lo split converters ------------------------
__global__ __launch_bounds__(256)
void convert_x_kernel(const float* __restrict__ X) {
    const int bt = blockIdx.x;
    const int b = bt >> 7;
    const int t = bt & 127;
    const float4 v = ((const float4*)(X + (size_t)bt * DD))[threadIdx.x];
    __nv_bfloat16 hi4[4], lo4[4];
    hi4[0] = __float2bfloat16_rn(v.x); lo4[0] = __float2bfloat16_rn(v.x - __bfloat162float(hi4[0]));
    hi4[1] = __float2bfloat16_rn(v.y); lo4[1] = __float2bfloat16_rn(v.y - __bfloat162float(hi4[1]));
    hi4[2] = __float2bfloat16_rn(v.z); lo4[2] = __float2bfloat16_rn(v.z - __bfloat162float(hi4[2]));
    hi4[3] = __float2bfloat16_rn(v.w); lo4[3] = __float2bfloat16_rn(v.w - __bfloat162float(hi4[3]));
    const size_t base = ((size_t)t * BB + b) * KS + threadIdx.x * 4;
    *(uint2*)&g_Xs[base]        = *(const uint2*)hi4;
    *(uint2*)&g_Xs[base + DD]   = *(const uint2*)lo4;
    *(uint2*)&g_Xs[base + 2*DD] = *(const uint2*)hi4;
}

__global__ __launch_bounds__(256)
void convert_w_kernel(const float* __restrict__ Wf, const float* __restrict__ Wb,
                      const float* __restrict__ bf, const float* __restrict__ bb) {
    const int c = blockIdx.x;
    const int dir = (c >= G4H);
    const int local = c - dir * G4H;
    const int j = local >> 2, gate = local & 3;
    const int srow = gate * HH + j;
    const float* src = dir ? (Wb + (size_t)srow * DD) : (Wf + (size_t)srow * DD);
    const float4 v = ((const float4*)src)[threadIdx.x];
    __nv_bfloat16 hi4[4], lo4[4];
    hi4[0] = __float2bfloat16_rn(v.x); lo4[0] = __float2bfloat16_rn(v.x - __bfloat162float(hi4[0]));
    hi4[1] = __float2bfloat16_rn(v.y); lo4[1] = __float2bfloat16_rn(v.y - __bfloat162float(hi4[1]));
    hi4[2] = __float2bfloat16_rn(v.z); lo4[2] = __float2bfloat16_rn(v.z - __bfloat162float(hi4[2]));
    hi4[3] = __float2bfloat16_rn(v.w); lo4[3] = __float2bfloat16_rn(v.w - __bfloat162float(hi4[3]));
    const size_t base = (size_t)c * KS + threadIdx.x * 4;
    *(uint2*)&g_Ws[base]        = *(const uint2*)hi4;
    *(uint2*)&g_Ws[base + DD]   = *(const uint2*)hi4;
    *(uint2*)&g_Ws[base + 2*DD] = *(const uint2*)lo4;
    if (threadIdx.x == 0)
        g_bias[c] = dir ? bb[srow] : bf[srow];
}

__global__ __launch_bounds__(128)
void convert_whh_kernel(const float* __restrict__ Wf, const float* __restrict__ Wb) {
    const int c   = blockIdx.x;
    const int dir = blockIdx.y;
    const int gate = c & 3, j = c >> 2;
    const float* __restrict__ W = dir ? Wb : Wf;
    const float4 v = ((const float4*)(W + (size_t)(gate * HH + j) * HH))[threadIdx.x];
    __nv_bfloat16 hi4[4], lo4[4];
    hi4[0] = __float2bfloat16_rn(v.x); lo4[0] = __float2bfloat16_rn(v.x - __bfloat162float(hi4[0]));
    hi4[1] = __float2bfloat16_rn(v.y); lo4[1] = __float2bfloat16_rn(v.y - __bfloat162float(hi4[1]));
    hi4[2] = __float2bfloat16_rn(v.z); lo4[2] = __float2bfloat16_rn(v.z - __bfloat162float(hi4[2]));
    hi4[3] = __float2bfloat16_rn(v.w); lo4[3] = __float2bfloat16_rn(v.w - __bfloat162float(hi4[3]));
    __nv_bfloat16* dst = &g_Whh[dir][(size_t)c * 1024];
    *(uint2*)&dst[threadIdx.x * 4]       = *(const uint2*)hi4;
    *(uint2*)&dst[512 + threadIdx.x * 4] = *(const uint2*)lo4;
}

// ---------------- input-projection GEMM: BK=64, 3-stage, 1 sync/iter ---------
#define SROW2 144
#define GA_TILE (128 * SROW2)       // 18432
#define GSTG (2 * GA_TILE)          // 36864 (A + B)
#define G_SMEM (3 * GSTG)           // 110592
#define GKT (KS / 64)               // 48

__global__ __launch_bounds__(256, 2)
void gemm_mma_kernel() {
    extern __shared__ __align__(16) char sm[];
    const uint32_t sbase = smem_u32(sm);

    const int tid  = threadIdx.x;
    const int wid  = tid >> 5;
    const int lane = tid & 31;
    const int nTile = blockIdx.x * 128;
    const int mTile = blockIdx.y * 128;

    const int m0 = (wid & 3) * 32;
    const int n0 = (wid >> 2) * 64;

    // load mapping: 1024 16B-chunks per tile (A and B each), 4 per thread
    const int lr = tid >> 3;          // rows 0..31 (chunk tid)
    const int lc8 = tid & 7;
    const uint32_t loff = (uint32_t)(lr * SROW2 + lc8 * 16);
    const __nv_bfloat16* __restrict__ gA = g_Xs + (size_t)mTile * KS;
    const __nv_bfloat16* __restrict__ gB = g_Ws + (size_t)nTile * KS;

    auto issue_stage = [&](int kt) {
        const uint32_t sa = sbase + (kt % 3) * GSTG;
        const uint32_t sb = sa + GA_TILE;
        const size_t kcol = (size_t)kt * 64 + lc8 * 8;
#pragma unroll
        for (int q = 0; q < 4; q++) {
            const int row = lr + q * 32;
            const uint32_t d = loff + (uint32_t)(q * 32 * SROW2);
            CPA16(sa + d, gA + (size_t)row * KS + kcol);
            CPA16(sb + d, gB + (size_t)row * KS + kcol);
        }
    };

    float acc[2][8][4];
#pragma unroll
    for (int i = 0; i < 2; i++)
#pragma unroll
        for (int j = 0; j < 8; j++)
#pragma unroll
            for (int q = 0; q < 4; q++) acc[i][j][q] = 0.f;

    const int r8 = lane & 7;
    const int tI = lane >> 3;
    const uint32_t aLaneOff = (uint32_t)((r8 + (tI & 1) * 8) * SROW2 + (tI >> 1) * 16);
    const uint32_t bLaneOff = (uint32_t)((r8 + (tI >> 1) * 8) * SROW2 + (tI & 1) * 16);

    issue_stage(0); CPA_COMMIT();
    issue_stage(1); CPA_COMMIT();

    for (int kt = 0; kt < GKT; kt++) {
        asm volatile("cp.async.wait_group 1;" ::: "memory");
        __syncthreads();

        const uint32_t sa = sbase + (kt % 3) * GSTG;
        const uint32_t sb = sa + GA_TILE;
#pragma unroll
        for (int kk = 0; kk < 4; kk++) {
            uint32_t afr[2][4], bfr[4][4];
#pragma unroll
            for (int mi = 0; mi < 2; mi++)
                ldmatrix_x4(afr[mi],
                            sa + (uint32_t)((m0 + mi * 16) * SROW2 + kk * 32) + aLaneOff);
#pragma unroll
            for (int nb = 0; nb < 4; nb++)
                ldmatrix_x4(bfr[nb],
                            sb + (uint32_t)((n0 + nb * 16) * SROW2 + kk * 32) + bLaneOff);
#pragma unroll
            for (int mi = 0; mi < 2; mi++)
#pragma unroll
                for (int ni = 0; ni < 8; ni++) {
                    const uint32_t* bp = &bfr[ni >> 1][(ni & 1) * 2];
                    mma16816(acc[mi][ni], afr[mi], bp[0], bp[1]);
                }
        }
        if (kt + 2 < GKT) issue_stage(kt + 2);
        CPA_COMMIT();
    }

    const int gid = lane >> 2;
    const int tig = lane & 3;
#pragma unroll
    for (int mi = 0; mi < 2; mi++) {
        const int m = mTile + m0 + mi * 16 + gid;
#pragma unroll
        for (int ni = 0; ni < 8; ni++) {
            const int n = nTile + n0 + ni * 8 + tig * 2;
            const float2 bv = *(const float2*)&g_bias[n];
            float2 o0 = make_float2(acc[mi][ni][0] + bv.x, acc[mi][ni][1] + bv.y);
            float2 o1 = make_float2(acc[mi][ni][2] + bv.x, acc[mi][ni][3] + bv.y);
            *(float2*)&g_G[(size_t)m * GNF + n]       = o0;
            *(float2*)&g_G[(size_t)(m + 8) * GNF + n] = o1;
        }
    }
}

// ---------------- persistent recurrence (R10 winner, unchanged) --------------
#define ST_A (64 * SROW2)          // 9216
#define ST_B (64 * SROW2)          // 9216
#define STG  (ST_A + ST_B)         // 18432
#define NST 6
#define R10_SMEM (NST * STG)       // 110592
#define NPAIR 12
#define SRBUF (64 * 68 * 4)

__global__ __launch_bounds__(256, 2)
void lstm_persistent(const int* __restrict__ x_len)
{
    extern __shared__ __align__(16) char sm[];
    const uint32_t sbase = smem_u32(sm);

    const int tid  = threadIdx.x;
    const int wid  = tid >> 5;
    const int lane = tid & 31;
    const int nTile = blockIdx.x * 64;
    const int b0    = blockIdx.y * 64;
    const int dir   = blockIdx.z;
    const int grp   = dir * 4 + blockIdx.y;

    const __nv_bfloat16* __restrict__ Wd = g_Whh[dir];
    float* __restrict__ outp = g_outd[dir];

    const int ksg = wid >> 2;
    const int w4  = wid & 3;
    const int m0  = (w4 & 1) * 32;
    const int n0  = (w4 >> 1) * 32;

    const int c0r = tid >> 3;
    const int c1r = (tid + 256) >> 3;
    const int c8  = (tid & 7);
    const uint32_t off0 = (uint32_t)(c0r * SROW2 + c8 * 16);
    const uint32_t off1 = (uint32_t)(c1r * SROW2 + c8 * 16);

    const int r8 = lane & 7;
    const int tI = lane >> 3;
    const uint32_t aLaneOff = (uint32_t)((r8 + (tI & 1) * 8) * SROW2 + (tI >> 1) * 16);
    const uint32_t bLaneOff = (uint32_t)((r8 + (tI >> 1) * 8) * SROW2 + (tI & 1) * 16);
    const int gid = lane >> 2;
    const int tig = lane & 3;
    const int jBase = nTile >> 2;

    float* __restrict__ sR0 = (float*)sm;
    float* __restrict__ sR1 = (float*)(sm + SRBUF);
    float* __restrict__ sRme = ksg ? sR1 : sR0;

    for (int t = 0; t < LL; t++) {
        const int p2 = t & 1;
        const __nv_bfloat16* __restrict__ hhi = g_hhi[dir][p2];
        const __nv_bfloat16* __restrict__ hlo = g_hlo[dir][p2];
        const float* __restrict__ hprev = g_h[dir][p2];
        const float* __restrict__ cprev = g_c[dir][p2];
        float* __restrict__ hnext = g_h[dir][p2 ^ 1];
        float* __restrict__ cnext = g_c[dir][p2 ^ 1];
        __nv_bfloat16* __restrict__ hhin = g_hhi[dir][p2 ^ 1];
        __nv_bfloat16* __restrict__ hlon = g_hlo[dir][p2 ^ 1];

        float4 gp[4];
#pragma unroll
        for (int it = 0; it < 4; it++) {
            const int idx = it * 256 + tid;
            const int bl = idx >> 4;
            const int jj = idx & 15;
            const int b  = b0 + bl;
            const int len = x_len[b];
            int tq = t;
            if (dir) { tq = len - 1 - t; if (tq < 0) tq = 0; }
            gp[it] = *(const float4*)(
                g_G + ((size_t)tq * BB + b) * GNF + dir * G4H + (size_t)(jBase + jj) * 4);
        }

        auto issue_stage = [&](int kt) {
            const int stage = kt % NST;
            const int seg  = kt >> 3;
            const int ktk  = kt & 7;
            const int acol = ktk * 64;
            const int bcol = (seg == 2) ? (512 + ktk * 64) : (ktk * 64);
            const __nv_bfloat16* __restrict__ hsrc = (seg == 1) ? hlo : hhi;
            const uint32_t sa = sbase + stage * STG;
            const uint32_t sb = sa + ST_A;
            CPA16(sa + off0, hsrc + (size_t)(b0 + c0r) * HH + acol + c8 * 8);
            CPA16(sa + off1, hsrc + (size_t)(b0 + c1r) * HH + acol + c8 * 8);
            CPA16(sb + off0, Wd + (size_t)(nTile + c0r) * 1024 + bcol + c8 * 8);
            CPA16(sb + off1, Wd + (size_t)(nTile + c1r) * 1024 + bcol + c8 * 8);
        };

        float acc[2][4][4];
#pragma unroll
        for (int i = 0; i < 2; i++)
#pragma unroll
            for (int j = 0; j < 4; j++)
#pragma unroll
                for (int q = 0; q < 4; q++) acc[i][j][q] = 0.f;

        issue_stage(0); issue_stage(1); CPA_COMMIT();
        issue_stage(2); issue_stage(3); CPA_COMMIT();

        for (int p = 0; p < NPAIR; p++) {
            asm volatile("cp.async.wait_group 1;" ::: "memory");
            __syncthreads();

            const int kt = 2 * p + ksg;
            const uint32_t sa = sbase + (kt % NST) * STG;
            const uint32_t sb = sa + ST_A;
#pragma unroll
            for (int kk = 0; kk < 4; kk++) {
                uint32_t afr[2][4], bfr[2][4];
#pragma unroll
                for (int mi = 0; mi < 2; mi++)
                    ldmatrix_x4(afr[mi],
                                sa + (uint32_t)((m0 + mi * 16) * SROW2 + kk * 32) + aLaneOff);
#pragma unroll
                for (int nb = 0; nb < 2; nb++)
                    ldmatrix_x4(bfr[nb],
                                sb + (uint32_t)((n0 + nb * 16) * SROW2 + kk * 32) + bLaneOff);
#pragma unroll
                for (int mi = 0; mi < 2; mi++)
#pragma unroll
                    for (int ni = 0; ni < 4; ni++) {
                        const uint32_t* bp = &bfr[ni >> 1][(ni & 1) * 2];
                        mma16816(acc[mi][ni], afr[mi], bp[0], bp[1]);
                    }
            }
            if (p + 2 < NPAIR) { issue_stage(2 * p + 4); issue_stage(2 * p + 5); }
            CPA_COMMIT();
        }
        asm volatile("cp.async.wait_group 0;" ::: "memory");
        __syncthreads();

#pragma unroll
        for (int mi = 0; mi < 2; mi++) {
            const int row = m0 + mi * 16 + gid;
#pragma unroll
            for (int ni = 0; ni < 4; ni++) {
                const int col = n0 + ni * 8 + tig * 2;
                sRme[row * 68 + col]           = acc[mi][ni][0];
                sRme[row * 68 + col + 1]       = acc[mi][ni][1];
                sRme[(row + 8) * 68 + col]     = acc[mi][ni][2];
                sRme[(row + 8) * 68 + col + 1] = acc[mi][ni][3];
            }
        }
        __syncthreads();

#pragma unroll
        for (int it = 0; it < 4; it++) {
            const int idx = it * 256 + tid;
            const int bl = idx >> 4;
            const int jj = idx & 15;
            const int b  = b0 + bl;
            const int j  = jBase + jj;
            const int len = x_len[b];
            const float4 r0 = *(const float4*)&sR0[bl * 68 + jj * 4];
            const float4 r1 = *(const float4*)&sR1[bl * 68 + jj * 4];
            float i_ = fsigmoid(r0.x + r1.x + gp[it].x);
            float f_ = fsigmoid(r0.y + r1.y + gp[it].y);
            float g_ = ftanh(r0.z + r1.z + gp[it].z);
            float o_ = fsigmoid(r0.w + r1.w + gp[it].w);
            const size_t hc = (size_t)b * HH + j;
            float cp = cprev[hc];
            float hp = hprev[hc];
            float cn = f_ * cp + i_ * g_;
            float hn = o_ * ftanh(cn);
            const bool valid = (t < len);
            const float ho = valid ? hn : hp;
            const float co = valid ? cn : cp;
            hnext[hc] = ho;
            cnext[hc] = co;
            __nv_bfloat16 hi = __float2bfloat16_rn(ho);
            hhin[hc] = hi;
            hlon[hc] = __float2bfloat16_rn(ho - __bfloat162float(hi));
            outp[((size_t)b * LL + t) * HH + j] = valid ? hn : 0.f;
        }

        group_barrier(grp, t);
    }
}

// ---------------- attention + head ------------------------------------------
__global__ __launch_bounds__(256)
void final_kernel(const float* __restrict__ x, const int* __restrict__ x_len,
                  const float* __restrict__ target_word,
                  const float* __restrict__ W_h, const float* __restrict__ b_tanh,
                  const float* __restrict__ W_lin, const float* __restrict__ b_lin,
                  const float* __restrict__ W_out, const float* __restrict__ b_out,
                  float* __restrict__ out)
{
    __shared__ float s_u[LL];
    __shared__ float s_ctx[2 * HH];
    __shared__ float s_lin[512];
    __shared__ float s_red[8];
    __shared__ float s_twdot;

    const int b    = blockIdx.x;
    const int tid  = threadIdx.x;
    const int warp = tid >> 5;
    const int lane = tid & 31;
    const int len  = x_len[b];

    {
        float partial = 0.f;
        for (int d = tid; d < DD; d += 256) {
            float s = 0.f;
#pragma unroll
            for (int k = 0; k < 5; k++)
                s += target_word[((size_t)b * 5 + k) * DD + d];
            partial = fmaf(s * 0.2f, W_h[DD + d], partial);
        }
#pragma unroll
        for (int off = 16; off; off >>= 1)
            partial += __shfl_xor_sync(0xffffffffu, partial, off);
        if (lane == 0) s_red[warp] = partial;
        __syncthreads();
        if (tid == 0) {
            float s = 0.f;
            for (int w = 0; w < 8; w++) s += s_red[w];
            s_twdot = s;
        }
        __syncthreads();
    }
    const float twdot = s_twdot;

    for (int i = 0; i < 16; i++) {
        const int t = warp * 16 + i;
        const float* xe = x + ((size_t)b * LL + t) * DD;
        float a = 0.f;
#pragma unroll 8
        for (int q = 0; q < 32; q++) {
            int d = lane + q * 32;
            a = fmaf(xe[d], W_h[d], a);
        }
#pragma unroll
        for (int off = 16; off; off >>= 1)
            a += __shfl_xor_sync(0xffffffffu, a, off);
        if (lane == 0)
            s_u[t] = (t < len) ? (a + twdot + b_tanh[t]) : -1e6f;
    }
    __syncthreads();

    if (warp == 0) {
        float v[4];
#pragma unroll
        for (int q = 0; q < 4; q++) v[q] = s_u[lane + q * 32];
        float m = fmaxf(fmaxf(v[0], v[1]), fmaxf(v[2], v[3]));
#pragma unroll
        for (int off = 16; off; off >>= 1)
            m = fmaxf(m, __shfl_xor_sync(0xffffffffu, m, off));
        float e[4], s = 0.f;
#pragma unroll
        for (int q = 0; q < 4; q++) { e[q] = expf(v[q] - m); s += e[q]; }
#pragma unroll
        for (int off = 16; off; off >>= 1)
            s += __shfl_xor_sync(0xffffffffu, s, off);
        float inv = 1.f / s;
#pragma unroll
        for (int q = 0; q < 4; q++) s_u[lane + q * 32] = e[q] * inv;
    }
    __syncthreads();

    {
        float accj[4] = {0.f, 0.f, 0.f, 0.f};
        const float* outf = g_outd[0] + (size_t)b * LL * HH;
        const float* outb = g_outd[1] + (size_t)b * LL * HH;
        for (int t = 0; t < LL; t++) {
            const float a = s_u[t];
            int t2 = len - 1 - t;
            if (t2 < 0) t2 = 0;
#pragma unroll
            for (int q = 0; q < 4; q++) {
                const int j = tid + q * 256;
                float hv;
                if (j < HH) hv = outf[(size_t)t * HH + j];
                else        hv = outb[(size_t)t2 * HH + (j - HH)];
                accj[q] = fmaf(a, hv, accj[q]);
            }
        }
#pragma unroll
        for (int q = 0; q < 4; q++) s_ctx[tid + q * 256] = accj[q];
    }
    __syncthreads();

    for (int i = 0; i < 64; i++) {
        const int o = warp * 64 + i;
        const float* wr = W_lin + (size_t)o * (2 * HH);
        float a = 0.f;
#pragma unroll 8
        for (int q = 0; q < 32; q++) {
            int d = lane + q * 32;
            a = fmaf(s_ctx[d], wr[d], a);
        }
#pragma unroll
        for (int off = 16; off; off >>= 1)
            a += __shfl_xor_sync(0xffffffffu, a, off);
        if (lane == 0) s_lin[o] = fmaxf(a + b_lin[o], 0.f);
    }
    __syncthreads();

    if (warp == 0) {
#pragma unroll
        for (int o = 0; o < 3; o++) {
            const float* wr = W_out + (size_t)o * 512;
            float a = 0.f;
#pragma unroll
            for (int q = 0; q < 16; q++) {
                int d = lane + q * 32;
                a = fmaf(s_lin[d], wr[d], a);
            }
#pragma unroll
            for (int off = 16; off; off >>= 1)
                a += __shfl_xor_sync(0xffffffffu, a, off);
            if (lane == 0) out[b * 3 + o] = a + b_out[o];
        }
    }
}

// ---------------- launch -----------------------------------------------------
extern "C" void kernel_launch(void* const* d_in, const int* in_sizes, int n_in,
                              void* d_out, int out_size)
{
    const float* x           = (const float*)d_in[0];
    const int*   x_len       = (const int*)d_in[1];
    const float* target_word = (const float*)d_in[3];
    const float* W_ih_f      = (const float*)d_in[5];
    const float* W_hh_f      = (const float*)d_in[6];
    const float* b_f         = (const float*)d_in[7];
    const float* W_ih_b      = (const float*)d_in[8];
    const float* W_hh_b      = (const float*)d_in[9];
    const float* b_b         = (const float*)d_in[10];
    const float* W_h         = (const float*)d_in[11];
    const float* b_tanh      = (const float*)d_in[12];
    const float* W_lin       = (const float*)d_in[13];
    const float* b_lin       = (const float*)d_in[14];
    const float* W_out       = (const float*)d_in[15];
    const float* b_out       = (const float*)d_in[16];
    float* out = (float*)d_out;

    static bool attr_set = false;
    if (!attr_set) {
        cudaFuncSetAttribute(lstm_persistent,
                             cudaFuncAttributeMaxDynamicSharedMemorySize, R10_SMEM);
        cudaFuncSetAttribute(gemm_mma_kernel,
                             cudaFuncAttributeMaxDynamicSharedMemorySize, G_SMEM);
        attr_set = true;
    }

    init_hc_kernel<<<(BB * HH + 255) / 256, 256>>>();
    convert_x_kernel<<<BB * LL, 256>>>(x);
    convert_w_kernel<<<GNF, 256>>>(W_ih_f, W_ih_b, b_f, b_b);
    {
        dim3 wgrid(G4H, 2);
        convert_whh_kernel<<<wgrid, 128>>>(W_hh_f, W_hh_b);
    }

    dim3 ggrid(GNF / 128, MM_TOT / 128);   // (32, 256)
    gemm_mma_kernel<<<ggrid, 256, G_SMEM>>>();

    dim3 sgrid(G4H / 64, BB / 64, 2);      // (32, 4, 2) = 256 persistent blocks
    lstm_persistent<<<sgrid, 256, R10_SMEM>>>(x_len);

    final_kernel<<<BB, 256>>>(x, x_len, target_word, W_h, b_tanh,
                              W_lin, b_lin, W_out, b_out, out);
}

// round 12
// speedup vs baseline: 1.2562x; 1.0182x over previous
#include <cuda_runtime.h>
#include <cuda_bf16.h>
#include <math.h>
#include <stdint.h>

// Problem dims
#define BB 256
#define LL 128
#define DD 1024
#define HH 512
#define G4H 2048
#define GNF 4096
#define KS 3072
#define MM_TOT (LL * BB)

// ---------------- scratch (device globals) ----------------------------------
__device__ float g_G[(size_t)MM_TOT * GNF];
__device__ float g_outd[2][(size_t)BB * LL * HH];
__device__ __nv_bfloat16 g_hhi[2][2][(size_t)BB * HH];
__device__ __nv_bfloat16 g_hlo[2][2][(size_t)BB * HH];
__device__ __nv_bfloat16 g_Xs[(size_t)MM_TOT * KS];
__device__ __nv_bfloat16 g_Ws[(size_t)GNF * KS];
__device__ __nv_bfloat16 g_Whh[2][(size_t)G4H * 1024];
__device__ float g_bias[GNF];

struct GrpBar { unsigned int cnt; unsigned int gen; unsigned int pad[62]; };
__device__ GrpBar g_bars[8];

// ---------------- helpers ----------------------------------------------------
__device__ __forceinline__ uint32_t smem_u32(const void* p) {
    uint32_t a;
    asm("{ .reg .u64 t; cvta.to.shared.u64 t, %1; cvt.u32.u64 %0, t; }"
        : "=r"(a) : "l"(p));
    return a;
}
#define CPA16(dst, src) \
    asm volatile("cp.async.ca.shared.global [%0], [%1], 16;" :: "r"(dst), "l"(src))
#define CPA_COMMIT() asm volatile("cp.async.commit_group;" ::: "memory")

__device__ __forceinline__ void ldmatrix_x4(uint32_t* r, uint32_t addr) {
    asm volatile("ldmatrix.sync.aligned.m8n8.x4.shared.b16 {%0,%1,%2,%3}, [%4];"
                 : "=r"(r[0]), "=r"(r[1]), "=r"(r[2]), "=r"(r[3]) : "r"(addr));
}
__device__ __forceinline__ void mma16816(float* c, const uint32_t* a,
                                         uint32_t b0, uint32_t b1) {
    asm volatile(
        "mma.sync.aligned.m16n8k16.row.col.f32.bf16.bf16.f32 "
        "{%0,%1,%2,%3}, {%4,%5,%6,%7}, {%8,%9}, {%0,%1,%2,%3};"
        : "+f"(c[0]), "+f"(c[1]), "+f"(c[2]), "+f"(c[3])
        : "r"(a[0]), "r"(a[1]), "r"(a[2]), "r"(a[3]), "r"(b0), "r"(b1));
}
__device__ __forceinline__ float fsigmoid(float x) {
    return __fdividef(1.f, 1.f + __expf(-x));
}
__device__ __forceinline__ float ftanh(float x) {
    float e2 = __expf(2.f * x);
    return __fdividef(e2 - 1.f, e2 + 1.f);
}

__device__ __forceinline__ void group_barrier(int gid, int step) {
    __syncthreads();
    if (threadIdx.x == 0) {
        __threadfence();
        unsigned int a = atomicAdd(&g_bars[gid].cnt, 1u);
        if (a == 31u) {
            g_bars[gid].cnt = 0;
            __threadfence();
            atomicExch(&g_bars[gid].gen, (unsigned)(step + 1));
        } else {
            unsigned int g;
            do {
                asm volatile("ld.acquire.gpu.u32 %0, [%1];"
                             : "=r"(g) : "l"(&g_bars[gid].gen));
                if (g > (unsigned)step) break;
                __nanosleep(32);
            } while (true);
        }
    }
    __syncthreads();
}

// ---------------- init -------------------------------------------------------
__global__ void init_hc_kernel() {
    int i = blockIdx.x * blockDim.x + threadIdx.x;
    if (i < 8) { g_bars[i].cnt = 0; g_bars[i].gen = 0; }
    if (i < BB * HH) {
        g_hhi[0][0][i] = __float2bfloat16_rn(0.f);
        g_hhi[1][0][i] = __float2bfloat16_rn(0.f);
        g_hlo[0][0][i] = __float2bfloat16_rn(0.f);
        g_hlo[1][0][i] = __float2bfloat16_rn(0.f);
    }
}

// ---------------- fp32 -> bf16 hi/lo split converters ------------------------
__global__ __launch_bounds__(256)
void convert_x_kernel(const float* __restrict__ X) {
    const int bt = blockIdx.x;
    const int b = bt >> 7;
    const int t = bt & 127;
    const float4 v = ((const float4*)(X + (size_t)bt * DD))[threadIdx.x];
    __nv_bfloat16 hi4[4], lo4[4];
    hi4[0] = __float2bfloat16_rn(v.x); lo4[0] = __float2bfloat16_rn(v.x - __bfloat162float(hi4[0]));
    hi4[1] = __float2bfloat16_rn(v.y); lo4[1] = __float2bfloat16_rn(v.y - __bfloat162float(hi4[1]));
    hi4[2] = __float2bfloat16_rn(v.z); lo4[2] = __float2bfloat16_rn(v.z - __bfloat162float(hi4[2]));
    hi4[3] = __float2bfloat16_rn(v.w); lo4[3] = __float2bfloat16_rn(v.w - __bfloat162float(hi4[3]));
    const size_t base = ((size_t)t * BB + b) * KS + threadIdx.x * 4;
    *(uint2*)&g_Xs[base]        = *(const uint2*)hi4;
    *(uint2*)&g_Xs[base + DD]   = *(const uint2*)lo4;
    *(uint2*)&g_Xs[base + 2*DD] = *(const uint2*)hi4;
}

__global__ __launch_bounds__(256)
void convert_w_kernel(const float* __restrict__ Wf, const float* __restrict__ Wb,
                      const float* __restrict__ bf, const float* __restrict__ bb) {
    const int c = blockIdx.x;
    const int dir = (c >= G4H);
    const int local = c - dir * G4H;
    const int j = local >> 2, gate = local & 3;
    const int srow = gate * HH + j;
    const float* src = dir ? (Wb + (size_t)srow * DD) : (Wf + (size_t)srow * DD);
    const float4 v = ((const float4*)src)[threadIdx.x];
    __nv_bfloat16 hi4[4], lo4[4];
    hi4[0] = __float2bfloat16_rn(v.x); lo4[0] = __float2bfloat16_rn(v.x - __bfloat162float(hi4[0]));
    hi4[1] = __float2bfloat16_rn(v.y); lo4[1] = __float2bfloat16_rn(v.y - __bfloat162float(hi4[1]));
    hi4[2] = __float2bfloat16_rn(v.z); lo4[2] = __float2bfloat16_rn(v.z - __bfloat162float(hi4[2]));
    hi4[3] = __float2bfloat16_rn(v.w); lo4[3] = __float2bfloat16_rn(v.w - __bfloat162float(hi4[3]));
    const size_t base = (size_t)c * KS + threadIdx.x * 4;
    *(uint2*)&g_Ws[base]        = *(const uint2*)hi4;
    *(uint2*)&g_Ws[base + DD]   = *(const uint2*)hi4;
    *(uint2*)&g_Ws[base + 2*DD] = *(const uint2*)lo4;
    if (threadIdx.x == 0)
        g_bias[c] = dir ? bb[srow] : bf[srow];
}

__global__ __launch_bounds__(128)
void convert_whh_kernel(const float* __restrict__ Wf, const float* __restrict__ Wb) {
    const int c   = blockIdx.x;
    const int dir = blockIdx.y;
    const int gate = c & 3, j = c >> 2;
    const float* __restrict__ W = dir ? Wb : Wf;
    const float4 v = ((const float4*)(W + (size_t)(gate * HH + j) * HH))[threadIdx.x];
    __nv_bfloat16 hi4[4], lo4[4];
    hi4[0] = __float2bfloat16_rn(v.x); lo4[0] = __float2bfloat16_rn(v.x - __bfloat162float(hi4[0]));
    hi4[1] = __float2bfloat16_rn(v.y); lo4[1] = __float2bfloat16_rn(v.y - __bfloat162float(hi4[1]));
    hi4[2] = __float2bfloat16_rn(v.z); lo4[2] = __float2bfloat16_rn(v.z - __bfloat162float(hi4[2]));
    hi4[3] = __float2bfloat16_rn(v.w); lo4[3] = __float2bfloat16_rn(v.w - __bfloat162float(hi4[3]));
    __nv_bfloat16* dst = &g_Whh[dir][(size_t)c * 1024];
    *(uint2*)&dst[threadIdx.x * 4]       = *(const uint2*)hi4;
    *(uint2*)&dst[512 + threadIdx.x * 4] = *(const uint2*)lo4;
}

// ---------------- input-projection GEMM (R11 winner, unchanged) --------------
#define SROW2 144
#define GA_TILE (128 * SROW2)
#define GSTG (2 * GA_TILE)
#define G_SMEM (3 * GSTG)
#define GKT (KS / 64)

__global__ __launch_bounds__(256, 2)
void gemm_mma_kernel() {
    extern __shared__ __align__(16) char sm[];
    const uint32_t sbase = smem_u32(sm);

    const int tid  = threadIdx.x;
    const int wid  = tid >> 5;
    const int lane = tid & 31;
    const int nTile = blockIdx.x * 128;
    const int mTile = blockIdx.y * 128;

    const int m0 = (wid & 3) * 32;
    const int n0 = (wid >> 2) * 64;

    const int lr = tid >> 3;
    const int lc8 = tid & 7;
    const uint32_t loff = (uint32_t)(lr * SROW2 + lc8 * 16);
    const __nv_bfloat16* __restrict__ gA = g_Xs + (size_t)mTile * KS;
    const __nv_bfloat16* __restrict__ gB = g_Ws + (size_t)nTile * KS;

    auto issue_stage = [&](int kt) {
        const uint32_t sa = sbase + (kt % 3) * GSTG;
        const uint32_t sb = sa + GA_TILE;
        const size_t kcol = (size_t)kt * 64 + lc8 * 8;
#pragma unroll
        for (int q = 0; q < 4; q++) {
            const int row = lr + q * 32;
            const uint32_t d = loff + (uint32_t)(q * 32 * SROW2);
            CPA16(sa + d, gA + (size_t)row * KS + kcol);
            CPA16(sb + d, gB + (size_t)row * KS + kcol);
        }
    };

    float acc[2][8][4];
#pragma unroll
    for (int i = 0; i < 2; i++)
#pragma unroll
        for (int j = 0; j < 8; j++)
#pragma unroll
            for (int q = 0; q < 4; q++) acc[i][j][q] = 0.f;

    const int r8 = lane & 7;
    const int tI = lane >> 3;
    const uint32_t aLaneOff = (uint32_t)((r8 + (tI & 1) * 8) * SROW2 + (tI >> 1) * 16);
    const uint32_t bLaneOff = (uint32_t)((r8 + (tI >> 1) * 8) * SROW2 + (tI & 1) * 16);

    issue_stage(0); CPA_COMMIT();
    issue_stage(1); CPA_COMMIT();

    for (int kt = 0; kt < GKT; kt++) {
        asm volatile("cp.async.wait_group 1;" ::: "memory");
        __syncthreads();

        const uint32_t sa = sbase + (kt % 3) * GSTG;
        const uint32_t sb = sa + GA_TILE;
#pragma unroll
        for (int kk = 0; kk < 4; kk++) {
            uint32_t afr[2][4], bfr[4][4];
#pragma unroll
            for (int mi = 0; mi < 2; mi++)
                ldmatrix_x4(afr[mi],
                            sa + (uint32_t)((m0 + mi * 16) * SROW2 + kk * 32) + aLaneOff);
#pragma unroll
            for (int nb = 0; nb < 4; nb++)
                ldmatrix_x4(bfr[nb],
                            sb + (uint32_t)((n0 + nb * 16) * SROW2 + kk * 32) + bLaneOff);
#pragma unroll
            for (int mi = 0; mi < 2; mi++)
#pragma unroll
                for (int ni = 0; ni < 8; ni++) {
                    const uint32_t* bp = &bfr[ni >> 1][(ni & 1) * 2];
                    mma16816(acc[mi][ni], afr[mi], bp[0], bp[1]);
                }
        }
        if (kt + 2 < GKT) issue_stage(kt + 2);
        CPA_COMMIT();
    }

    const int gid = lane >> 2;
    const int tig = lane & 3;
#pragma unroll
    for (int mi = 0; mi < 2; mi++) {
        const int m = mTile + m0 + mi * 16 + gid;
#pragma unroll
        for (int ni = 0; ni < 8; ni++) {
            const int n = nTile + n0 + ni * 8 + tig * 2;
            const float2 bv = *(const float2*)&g_bias[n];
            float2 o0 = make_float2(acc[mi][ni][0] + bv.x, acc[mi][ni][1] + bv.y);
            float2 o1 = make_float2(acc[mi][ni][2] + bv.x, acc[mi][ni][3] + bv.y);
            *(float2*)&g_G[(size_t)m * GNF + n]       = o0;
            *(float2*)&g_G[(size_t)(m + 8) * GNF + n] = o1;
        }
    }
}

// ---------------- persistent recurrence: reg-state + pre-barrier B prefetch --
#define ST_A (64 * SROW2)          // 9216
#define ST_B (64 * SROW2)          // 9216
#define STG  (ST_A + ST_B)         // 18432
#define NST 6
#define R12_SMEM (NST * STG)       // 110592
#define NPAIR 12
#define SRBUF (64 * 68 * 4)        // 17408
#define SROFF (4 * STG)            // sR overlays stages 4..5

__global__ __launch_bounds__(256, 2)
void lstm_persistent(const int* __restrict__ x_len)
{
    extern __shared__ __align__(16) char sm[];
    const uint32_t sbase = smem_u32(sm);

    const int tid  = threadIdx.x;
    const int wid  = tid >> 5;
    const int lane = tid & 31;
    const int nTile = blockIdx.x * 64;
    const int b0    = blockIdx.y * 64;
    const int dir   = blockIdx.z;
    const int grp   = dir * 4 + blockIdx.y;

    const __nv_bfloat16* __restrict__ Wd = g_Whh[dir];
    float* __restrict__ outp = g_outd[dir];

    const int ksg = wid >> 2;
    const int w4  = wid & 3;
    const int m0  = (w4 & 1) * 32;
    const int n0  = (w4 >> 1) * 32;

    const int c0r = tid >> 3;
    const int c1r = (tid + 256) >> 3;
    const int c8  = (tid & 7);
    const uint32_t off0 = (uint32_t)(c0r * SROW2 + c8 * 16);
    const uint32_t off1 = (uint32_t)(c1r * SROW2 + c8 * 16);

    const int r8 = lane & 7;
    const int tI = lane >> 3;
    const uint32_t aLaneOff = (uint32_t)((r8 + (tI & 1) * 8) * SROW2 + (tI >> 1) * 16);
    const uint32_t bLaneOff = (uint32_t)((r8 + (tI >> 1) * 8) * SROW2 + (tI & 1) * 16);
    const int gid = lane >> 2;
    const int tig = lane & 3;
    const int jBase = nTile >> 2;

    float* __restrict__ sR0 = (float*)(sm + SROFF);
    float* __restrict__ sR1 = (float*)(sm + SROFF + SRBUF);
    float* __restrict__ sRme = ksg ? sR1 : sR0;

    // per-thread persistent LSTM state: 4 (b,j) elements each
    float hreg[4] = {0.f, 0.f, 0.f, 0.f};
    float creg[4] = {0.f, 0.f, 0.f, 0.f};

    // B-only issue for a k-tile (weights; step-invariant addresses)
    auto issue_B = [&](int kt) {
        const int stage = kt % NST;
        const int seg  = kt >> 3;
        const int ktk  = kt & 7;
        const int bcol = (seg == 2) ? (512 + ktk * 64) : (ktk * 64);
        const uint32_t sb = sbase + stage * STG + ST_A;
        CPA16(sb + off0, Wd + (size_t)(nTile + c0r) * 1024 + bcol + c8 * 8);
        CPA16(sb + off1, Wd + (size_t)(nTile + c1r) * 1024 + bcol + c8 * 8);
    };

    // first-step prologue B (stages 0..3) in one group
    issue_B(0); issue_B(1); issue_B(2); issue_B(3); CPA_COMMIT();

    for (int t = 0; t < LL; t++) {
        const int p2 = t & 1;
        const __nv_bfloat16* __restrict__ hhi = g_hhi[dir][p2];
        const __nv_bfloat16* __restrict__ hlo = g_hlo[dir][p2];
        __nv_bfloat16* __restrict__ hhin = g_hhi[dir][p2 ^ 1];
        __nv_bfloat16* __restrict__ hlon = g_hlo[dir][p2 ^ 1];

        // A-only issue for a k-tile (depends on h(t))
        auto issue_A = [&](int kt) {
            const int stage = kt % NST;
            const int seg  = kt >> 3;
            const int acol = (kt & 7) * 64;
            const __nv_bfloat16* __restrict__ hsrc = (seg == 1) ? hlo : hhi;
            const uint32_t sa = sbase + stage * STG;
            CPA16(sa + off0, hsrc + (size_t)(b0 + c0r) * HH + acol + c8 * 8);
            CPA16(sa + off1, hsrc + (size_t)(b0 + c1r) * HH + acol + c8 * 8);
        };
        auto issue_AB = [&](int kt) {
            issue_A(kt); issue_B(kt);
        };

        // prefetch G (independent of h)
        float4 gp[4];
#pragma unroll
        for (int it = 0; it < 4; it++) {
            const int idx = it * 256 + tid;
            const int bl = idx >> 4;
            const int jj = idx & 15;
            const int b  = b0 + bl;
            const int len = x_len[b];
            int tq = t;
            if (dir) { tq = len - 1 - t; if (tq < 0) tq = 0; }
            gp[it] = *(const float4*)(
                g_G + ((size_t)tq * BB + b) * GNF + dir * G4H + (size_t)(jBase + jj) * 4);
        }

        float acc[2][4][4];
#pragma unroll
        for (int i = 0; i < 2; i++)
#pragma unroll
            for (int j = 0; j < 4; j++)
#pragma unroll
                for (int q = 0; q < 4; q++) acc[i][j][q] = 0.f;

        // post-barrier A prologue
        issue_A(0); issue_A(1); CPA_COMMIT();
        issue_A(2); issue_A(3); CPA_COMMIT();

        for (int p = 0; p < NPAIR; p++) {
            asm volatile("cp.async.wait_group 1;" ::: "memory");
            __syncthreads();

            const int kt = 2 * p + ksg;
            const uint32_t sa = sbase + (kt % NST) * STG;
            const uint32_t sb = sa + ST_A;
#pragma unroll
            for (int kk = 0; kk < 4; kk++) {
                uint32_t afr[2][4], bfr[2][4];
#pragma unroll
                for (int mi = 0; mi < 2; mi++)
                    ldmatrix_x4(afr[mi],
                                sa + (uint32_t)((m0 + mi * 16) * SROW2 + kk * 32) + aLaneOff);
#pragma unroll
                for (int nb = 0; nb < 2; nb++)
                    ldmatrix_x4(bfr[nb],
                                sb + (uint32_t)((n0 + nb * 16) * SROW2 + kk * 32) + bLaneOff);
#pragma unroll
                for (int mi = 0; mi < 2; mi++)
#pragma unroll
                    for (int ni = 0; ni < 4; ni++) {
                        const uint32_t* bp = &bfr[ni >> 1][(ni & 1) * 2];
                        mma16816(acc[mi][ni], afr[mi], bp[0], bp[1]);
                    }
            }
            if (p + 2 < NPAIR) { issue_AB(2 * p + 4); issue_AB(2 * p + 5); }
            CPA_COMMIT();
        }
        asm volatile("cp.async.wait_group 0;" ::: "memory");
        __syncthreads();

        // stage R through smem (stages 4..5 region; reads completed at last pair)
#pragma unroll
        for (int mi = 0; mi < 2; mi++) {
            const int row = m0 + mi * 16 + gid;
#pragma unroll
            for (int ni = 0; ni < 4; ni++) {
                const int col = n0 + ni * 8 + tig * 2;
                sRme[row * 68 + col]           = acc[mi][ni][0];
                sRme[row * 68 + col + 1]       = acc[mi][ni][1];
                sRme[(row + 8) * 68 + col]     = acc[mi][ni][2];
                sRme[(row + 8) * 68 + col + 1] = acc[mi][ni][3];
            }
        }
        __syncthreads();

        // fused LSTM pointwise: h/c in registers, no state round-trips
#pragma unroll
        for (int it = 0; it < 4; it++) {
            const int idx = it * 256 + tid;
            const int bl = idx >> 4;
            const int jj = idx & 15;
            const int b  = b0 + bl;
            const int j  = jBase + jj;
            const int len = x_len[b];
            const float4 r0 = *(const float4*)&sR0[bl * 68 + jj * 4];
            const float4 r1 = *(const float4*)&sR1[bl * 68 + jj * 4];
            float i_ = fsigmoid(r0.x + r1.x + gp[it].x);
            float f_ = fsigmoid(r0.y + r1.y + gp[it].y);
            float g_ = ftanh(r0.z + r1.z + gp[it].z);
            float o_ = fsigmoid(r0.w + r1.w + gp[it].w);
            float cn = f_ * creg[it] + i_ * g_;
            float hn = o_ * ftanh(cn);
            const bool valid = (t < len);
            if (valid) { creg[it] = cn; hreg[it] = hn; }
            const float ho = hreg[it];
            const size_t hc = (size_t)b * HH + j;
            __nv_bfloat16 hi = __float2bfloat16_rn(ho);
            hhin[hc] = hi;
            hlon[hc] = __float2bfloat16_rn(ho - __bfloat162float(hi));
            outp[((size_t)b * LL + t) * HH + j] = valid ? hn : 0.f;
        }

        // pre-barrier weight prefetch for next step (stages 0..3 B halves)
        if (t + 1 < LL) {
            issue_B(0); issue_B(1); issue_B(2); issue_B(3);
        }
        CPA_COMMIT();

        group_barrier(grp, t);
    }
}

// ---------------- attention + head ------------------------------------------
__global__ __launch_bounds__(256)
void final_kernel(const float* __restrict__ x, const int* __restrict__ x_len,
                  const float* __restrict__ target_word,
                  const float* __restrict__ W_h, const float* __restrict__ b_tanh,
                  const float* __restrict__ W_lin, const float* __restrict__ b_lin,
                  const float* __restrict__ W_out, const float* __restrict__ b_out,
                  float* __restrict__ out)
{
    __shared__ float s_u[LL];
    __shared__ float s_ctx[2 * HH];
    __shared__ float s_lin[512];
    __shared__ float s_red[8];
    __shared__ float s_twdot;

    const int b    = blockIdx.x;
    const int tid  = threadIdx.x;
    const int warp = tid >> 5;
    const int lane = tid & 31;
    const int len  = x_len[b];

    {
        float partial = 0.f;
        for (int d = tid; d < DD; d += 256) {
            float s = 0.f;
#pragma unroll
            for (int k = 0; k < 5; k++)
                s += target_word[((size_t)b * 5 + k) * DD + d];
            partial = fmaf(s * 0.2f, W_h[DD + d], partial);
        }
#pragma unroll
        for (int off = 16; off; off >>= 1)
            partial += __shfl_xor_sync(0xffffffffu, partial, off);
        if (lane == 0) s_red[warp] = partial;
        __syncthreads();
        if (tid == 0) {
            float s = 0.f;
            for (int w = 0; w < 8; w++) s += s_red[w];
            s_twdot = s;
        }
        __syncthreads();
    }
    const float twdot = s_twdot;

    for (int i = 0; i < 16; i++) {
        const int t = warp * 16 + i;
        const float* xe = x + ((size_t)b * LL + t) * DD;
        float a = 0.f;
#pragma unroll 8
        for (int q = 0; q < 32; q++) {
            int d = lane + q * 32;
            a = fmaf(xe[d], W_h[d], a);
        }
#pragma unroll
        for (int off = 16; off; off >>= 1)
            a += __shfl_xor_sync(0xffffffffu, a, off);
        if (lane == 0)
            s_u[t] = (t < len) ? (a + twdot + b_tanh[t]) : -1e6f;
    }
    __syncthreads();

    if (warp == 0) {
        float v[4];
#pragma unroll
        for (int q = 0; q < 4; q++) v[q] = s_u[lane + q * 32];
        float m = fmaxf(fmaxf(v[0], v[1]), fmaxf(v[2], v[3]));
#pragma unroll
        for (int off = 16; off; off >>= 1)
            m = fmaxf(m, __shfl_xor_sync(0xffffffffu, m, off));
        float e[4], s = 0.f;
#pragma unroll
        for (int q = 0; q < 4; q++) { e[q] = expf(v[q] - m); s += e[q]; }
#pragma unroll
        for (int off = 16; off; off >>= 1)
            s += __shfl_xor_sync(0xffffffffu, s, off);
        float inv = 1.f / s;
#pragma unroll
        for (int q = 0; q < 4; q++) s_u[lane + q * 32] = e[q] * inv;
    }
    __syncthreads();

    {
        float accj[4] = {0.f, 0.f, 0.f, 0.f};
        const float* outf = g_outd[0] + (size_t)b * LL * HH;
        const float* outb = g_outd[1] + (size_t)b * LL * HH;
        for (int t = 0; t < LL; t++) {
            const float a = s_u[t];
            int t2 = len - 1 - t;
            if (t2 < 0) t2 = 0;
#pragma unroll
            for (int q = 0; q < 4; q++) {
                const int j = tid + q * 256;
                float hv;
                if (j < HH) hv = outf[(size_t)t * HH + j];
                else        hv = outb[(size_t)t2 * HH + (j - HH)];
                accj[q] = fmaf(a, hv, accj[q]);
            }
        }
#pragma unroll
        for (int q = 0; q < 4; q++) s_ctx[tid + q * 256] = accj[q];
    }
    __syncthreads();

    for (int i = 0; i < 64; i++) {
        const int o = warp * 64 + i;
        const float* wr = W_lin + (size_t)o * (2 * HH);
        float a = 0.f;
#pragma unroll 8
        for (int q = 0; q < 32; q++) {
            int d = lane + q * 32;
            a = fmaf(s_ctx[d], wr[d], a);
        }
#pragma unroll
        for (int off = 16; off; off >>= 1)
            a += __shfl_xor_sync(0xffffffffu, a, off);
        if (lane == 0) s_lin[o] = fmaxf(a + b_lin[o], 0.f);
    }
    __syncthreads();

    if (warp == 0) {
#pragma unroll
        for (int o = 0; o < 3; o++) {
            const float* wr = W_out + (size_t)o * 512;
            float a = 0.f;
#pragma unroll
            for (int q = 0; q < 16; q++) {
                int d = lane + q * 32;
                a = fmaf(s_lin[d], wr[d], a);
            }
#pragma unroll
            for (int off = 16; off; off >>= 1)
                a += __shfl_xor_sync(0xffffffffu, a, off);
            if (lane == 0) out[b * 3 + o] = a + b_out[o];
        }
    }
}

// ---------------- launch -----------------------------------------------------
extern "C" void kernel_launch(void* const* d_in, const int* in_sizes, int n_in,
                              void* d_out, int out_size)
{
    const float* x           = (const float*)d_in[0];
    const int*   x_len       = (const int*)d_in[1];
    const float* target_word = (const float*)d_in[3];
    const float* W_ih_f      = (const float*)d_in[5];
    const float* W_hh_f      = (const float*)d_in[6];
    const float* b_f         = (const float*)d_in[7];
    const float* W_ih_b      = (const float*)d_in[8];
    const float* W_hh_b      = (const float*)d_in[9];
    const float* b_b         = (const float*)d_in[10];
    const float* W_h         = (const float*)d_in[11];
    const float* b_tanh      = (const float*)d_in[12];
    const float* W_lin       = (const float*)d_in[13];
    const float* b_lin       = (const float*)d_in[14];
    const float* W_out       = (const float*)d_in[15];
    const float* b_out       = (const float*)d_in[16];
    float* out = (float*)d_out;

    static bool attr_set = false;
    if (!attr_set) {
        cudaFuncSetAttribute(lstm_persistent,
                             cudaFuncAttributeMaxDynamicSharedMemorySize, R12_SMEM);
        cudaFuncSetAttribute(gemm_mma_kernel,
                             cudaFuncAttributeMaxDynamicSharedMemorySize, G_SMEM);
        attr_set = true;
    }

    init_hc_kernel<<<(BB * HH + 255) / 256, 256>>>();
    convert_x_kernel<<<BB * LL, 256>>>(x);
    convert_w_kernel<<<GNF, 256>>>(W_ih_f, W_ih_b, b_f, b_b);
    {
        dim3 wgrid(G4H, 2);
        convert_whh_kernel<<<wgrid, 128>>>(W_hh_f, W_hh_b);
    }

    dim3 ggrid(GNF / 128, MM_TOT / 128);   // (32, 256)
    gemm_mma_kernel<<<ggrid, 256, G_SMEM>>>();

    dim3 sgrid(G4H / 64, BB / 64, 2);      // (32, 4, 2) = 256 persistent blocks
    lstm_persistent<<<sgrid, 256, R12_SMEM>>>(x_len);

    final_kernel<<<BB, 256>>>(x, x_len, target_word, W_h, b_tanh,
                              W_lin, b_lin, W_out, b_out, out);
}

// round 13
// speedup vs baseline: 1.3230x; 1.0531x over previous
#include <cuda_runtime.h>
#include <cuda_bf16.h>
#include <math.h>
#include <stdint.h>

// Problem dims
#define BB 256
#define LL 128
#define DD 1024
#define HH 512
#define G4H 2048
#define GNF 4096
#define KS2 2048            // compact [hi|lo] storage K
#define MM_TOT (LL * BB)

// ---------------- scratch (device globals) ----------------------------------
__device__ float g_G[(size_t)MM_TOT * GNF];
__device__ float g_outd[2][(size_t)BB * LL * HH];
__device__ __nv_bfloat16 g_hhi[2][2][(size_t)BB * HH];
__device__ __nv_bfloat16 g_hlo[2][2][(size_t)BB * HH];
__device__ __nv_bfloat16 g_Xs[(size_t)MM_TOT * KS2];   // [m][ hi(1024) | lo(1024) ]
__device__ __nv_bfloat16 g_Ws[(size_t)GNF * KS2];      // [c][ hi(1024) | lo(1024) ]
__device__ __nv_bfloat16 g_Whh[2][(size_t)G4H * 1024];
__device__ float g_bias[GNF];

struct GrpBar { unsigned int cnt; unsigned int gen; unsigned int pad[62]; };
__device__ GrpBar g_bars[8];

// ---------------- helpers ----------------------------------------------------
__device__ __forceinline__ uint32_t smem_u32(const void* p) {
    uint32_t a;
    asm("{ .reg .u64 t; cvta.to.shared.u64 t, %1; cvt.u32.u64 %0, t; }"
        : "=r"(a) : "l"(p));
    return a;
}
#define CPA16(dst, src) \
    asm volatile("cp.async.ca.shared.global [%0], [%1], 16;" :: "r"(dst), "l"(src))
#define CPA_COMMIT() asm volatile("cp.async.commit_group;" ::: "memory")

__device__ __forceinline__ void ldmatrix_x4(uint32_t* r, uint32_t addr) {
    asm volatile("ldmatrix.sync.aligned.m8n8.x4.shared.b16 {%0,%1,%2,%3}, [%4];"
                 : "=r"(r[0]), "=r"(r[1]), "=r"(r[2]), "=r"(r[3]) : "r"(addr));
}
__device__ __forceinline__ void mma16816(float* c, const uint32_t* a,
                                         uint32_t b0, uint32_t b1) {
    asm volatile(
        "mma.sync.aligned.m16n8k16.row.col.f32.bf16.bf16.f32 "
        "{%0,%1,%2,%3}, {%4,%5,%6,%7}, {%8,%9}, {%0,%1,%2,%3};"
        : "+f"(c[0]), "+f"(c[1]), "+f"(c[2]), "+f"(c[3])
        : "r"(a[0]), "r"(a[1]), "r"(a[2]), "r"(a[3]), "r"(b0), "r"(b1));
}
__device__ __forceinline__ float fsigmoid(float x) {
    return __fdividef(1.f, 1.f + __expf(-x));
}
__device__ __forceinline__ float ftanh(float x) {
    float e2 = __expf(2.f * x);
    return __fdividef(e2 - 1.f, e2 + 1.f);
}

__device__ __forceinline__ void group_barrier(int gid, int step) {
    __syncthreads();
    if (threadIdx.x == 0) {
        __threadfence();
        unsigned int a = atomicAdd(&g_bars[gid].cnt, 1u);
        if (a == 31u) {
            g_bars[gid].cnt = 0;
            __threadfence();
            atomicExch(&g_bars[gid].gen, (unsigned)(step + 1));
        } else {
            unsigned int g;
            do {
                asm volatile("ld.acquire.gpu.u32 %0, [%1];"
                             : "=r"(g) : "l"(&g_bars[gid].gen));
                if (g > (unsigned)step) break;
                __nanosleep(32);
            } while (true);
        }
    }
    __syncthreads();
}

// ---------------- init -------------------------------------------------------
__global__ void init_hc_kernel() {
    int i = blockIdx.x * blockDim.x + threadIdx.x;
    if (i < 8) { g_bars[i].cnt = 0; g_bars[i].gen = 0; }
    if (i < BB * HH) {
        g_hhi[0][0][i] = __float2bfloat16_rn(0.f);
        g_hhi[1][0][i] = __float2bfloat16_rn(0.f);
        g_hlo[0][0][i] = __float2bfloat16_rn(0.f);
        g_hlo[1][0][i] = __float2bfloat16_rn(0.f);
    }
}

// ---------------- fp32 -> bf16 hi/lo split converters ------------------------
__global__ __launch_bounds__(256)
void convert_x_kernel(const float* __restrict__ X) {
    const int bt = blockIdx.x;
    const int b = bt >> 7;
    const int t = bt & 127;
    const float4 v = ((const float4*)(X + (size_t)bt * DD))[threadIdx.x];
    __nv_bfloat16 hi4[4], lo4[4];
    hi4[0] = __float2bfloat16_rn(v.x); lo4[0] = __float2bfloat16_rn(v.x - __bfloat162float(hi4[0]));
    hi4[1] = __float2bfloat16_rn(v.y); lo4[1] = __float2bfloat16_rn(v.y - __bfloat162float(hi4[1]));
    hi4[2] = __float2bfloat16_rn(v.z); lo4[2] = __float2bfloat16_rn(v.z - __bfloat162float(hi4[2]));
    hi4[3] = __float2bfloat16_rn(v.w); lo4[3] = __float2bfloat16_rn(v.w - __bfloat162float(hi4[3]));
    const size_t base = ((size_t)t * BB + b) * KS2 + threadIdx.x * 4;
    *(uint2*)&g_Xs[base]      = *(const uint2*)hi4;
    *(uint2*)&g_Xs[base + DD] = *(const uint2*)lo4;
}

__global__ __launch_bounds__(256)
void convert_w_kernel(const float* __restrict__ Wf, const float* __restrict__ Wb,
                      const float* __restrict__ bf, const float* __restrict__ bb) {
    const int c = blockIdx.x;
    const int dir = (c >= G4H);
    const int local = c - dir * G4H;
    const int j = local >> 2, gate = local & 3;
    const int srow = gate * HH + j;
    const float* src = dir ? (Wb + (size_t)srow * DD) : (Wf + (size_t)srow * DD);
    const float4 v = ((const float4*)src)[threadIdx.x];
    __nv_bfloat16 hi4[4], lo4[4];
    hi4[0] = __float2bfloat16_rn(v.x); lo4[0] = __float2bfloat16_rn(v.x - __bfloat162float(hi4[0]));
    hi4[1] = __float2bfloat16_rn(v.y); lo4[1] = __float2bfloat16_rn(v.y - __bfloat162float(hi4[1]));
    hi4[2] = __float2bfloat16_rn(v.z); lo4[2] = __float2bfloat16_rn(v.z - __bfloat162float(hi4[2]));
    hi4[3] = __float2bfloat16_rn(v.w); lo4[3] = __float2bfloat16_rn(v.w - __bfloat162float(hi4[3]));
    const size_t base = (size_t)c * KS2 + threadIdx.x * 4;
    *(uint2*)&g_Ws[base]      = *(const uint2*)hi4;
    *(uint2*)&g_Ws[base + DD] = *(const uint2*)lo4;
    if (threadIdx.x == 0)
        g_bias[c] = dir ? bb[srow] : bf[srow];
}

__global__ __launch_bounds__(128)
void convert_whh_kernel(const float* __restrict__ Wf, const float* __restrict__ Wb) {
    const int c   = blockIdx.x;
    const int dir = blockIdx.y;
    const int gate = c & 3, j = c >> 2;
    const float* __restrict__ W = dir ? Wb : Wf;
    const float4 v = ((const float4*)(W + (size_t)(gate * HH + j) * HH))[threadIdx.x];
    __nv_bfloat16 hi4[4], lo4[4];
    hi4[0] = __float2bfloat16_rn(v.x); lo4[0] = __float2bfloat16_rn(v.x - __bfloat162float(hi4[0]));
    hi4[1] = __float2bfloat16_rn(v.y); lo4[1] = __float2bfloat16_rn(v.y - __bfloat162float(hi4[1]));
    hi4[2] = __float2bfloat16_rn(v.z); lo4[2] = __float2bfloat16_rn(v.z - __bfloat162float(hi4[2]));
    hi4[3] = __float2bfloat16_rn(v.w); lo4[3] = __float2bfloat16_rn(v.w - __bfloat162float(hi4[3]));
    __nv_bfloat16* dst = &g_Whh[dir][(size_t)c * 1024];
    *(uint2*)&dst[threadIdx.x * 4]       = *(const uint2*)hi4;
    *(uint2*)&dst[512 + threadIdx.x * 4] = *(const uint2*)lo4;
}

// ---------------- input-projection GEMM: 128x256 tile, 512 thr, 3-stage ------
// Logical K = 3072 (48 kt of 64): seg0 = A.hi x B.hi, seg1 = A.lo x B.hi,
// seg2 = A.hi x B.lo  (reads remapped into the compact [hi|lo] arrays).
#define SROW2 144
#define GA_TILE (128 * SROW2)        // 18432
#define GB_TILE (256 * SROW2)        // 36864
#define GSTG (GA_TILE + GB_TILE)     // 55296
#define G_SMEM (3 * GSTG)            // 165888
#define GKT 48

__global__ __launch_bounds__(512, 1)
void gemm_mma_kernel() {
    extern __shared__ __align__(16) char sm[];
    const uint32_t sbase = smem_u32(sm);

    const int tid  = threadIdx.x;
    const int wid  = tid >> 5;
    const int lane = tid & 31;
    const int nTile = blockIdx.x * 256;
    const int mTile = blockIdx.y * 128;

    // 16 warps: 2 m-halves x 8 n-strips, warp tile 64x32
    const int m0 = (wid & 1) * 64;
    const int n0 = (wid >> 1) * 32;

    // load mapping: A 1024 chunks (2/thread), B 2048 chunks (4/thread)
    const int lc8 = tid & 7;
    const int lr  = tid >> 3;            // 0..63
    const uint32_t aoff0 = (uint32_t)(lr * SROW2 + lc8 * 16);
    const uint32_t aoff1 = (uint32_t)((lr + 64) * SROW2 + lc8 * 16);
    const __nv_bfloat16* __restrict__ gA = g_Xs + (size_t)mTile * KS2;
    const __nv_bfloat16* __restrict__ gB = g_Ws + (size_t)nTile * KS2;

    auto issue_stage = [&](int kt) {
        const uint32_t sa = sbase + (kt % 3) * GSTG;
        const uint32_t sb = sa + GA_TILE;
        const int seg = kt >> 4;
        const int k64 = (kt & 15) * 64;
        const size_t acol = (size_t)((seg == 1) ? (DD + k64) : k64) + lc8 * 8;
        const size_t bcol = (size_t)((seg == 2) ? (DD + k64) : k64) + lc8 * 8;
        // A: rows lr and lr+64
        CPA16(sa + aoff0, gA + (size_t)lr * KS2 + acol);
        CPA16(sa + aoff1, gA + (size_t)(lr + 64) * KS2 + acol);
        // B: rows lr, lr+64, lr+128, lr+192
#pragma unroll
        for (int q = 0; q < 4; q++) {
            const int row = lr + q * 64;
            CPA16(sb + aoff0 + (uint32_t)(q * 64 * SROW2),
                  gB + (size_t)row * KS2 + bcol);
        }
    };

    float acc[4][4][4];
#pragma unroll
    for (int i = 0; i < 4; i++)
#pragma unroll
        for (int j = 0; j < 4; j++)
#pragma unroll
            for (int q = 0; q < 4; q++) acc[i][j][q] = 0.f;

    const int r8 = lane & 7;
    const int tI = lane >> 3;
    const uint32_t aLaneOff = (uint32_t)((r8 + (tI & 1) * 8) * SROW2 + (tI >> 1) * 16);
    const uint32_t bLaneOff = (uint32_t)((r8 + (tI >> 1) * 8) * SROW2 + (tI & 1) * 16);

    issue_stage(0); CPA_COMMIT();
    issue_stage(1); CPA_COMMIT();

    for (int kt = 0; kt < GKT; kt++) {
        asm volatile("cp.async.wait_group 1;" ::: "memory");
        __syncthreads();

        const uint32_t sa = sbase + (kt % 3) * GSTG;
        const uint32_t sb = sa + GA_TILE;
#pragma unroll
        for (int kk = 0; kk < 4; kk++) {
            uint32_t afr[4][4], bfr[2][4];
#pragma unroll
            for (int mi = 0; mi < 4; mi++)
                ldmatrix_x4(afr[mi],
                            sa + (uint32_t)((m0 + mi * 16) * SROW2 + kk * 32) + aLaneOff);
#pragma unroll
            for (int nb = 0; nb < 2; nb++)
                ldmatrix_x4(bfr[nb],
                            sb + (uint32_t)((n0 + nb * 16) * SROW2 + kk * 32) + bLaneOff);
#pragma unroll
            for (int mi = 0; mi < 4; mi++)
#pragma unroll
                for (int ni = 0; ni < 4; ni++) {
                    const uint32_t* bp = &bfr[ni >> 1][(ni & 1) * 2];
                    mma16816(acc[mi][ni], afr[mi], bp[0], bp[1]);
                }
        }
        if (kt + 2 < GKT) issue_stage(kt + 2);
        CPA_COMMIT();
    }

    const int gid = lane >> 2;
    const int tig = lane & 3;
#pragma unroll
    for (int mi = 0; mi < 4; mi++) {
        const int m = mTile + m0 + mi * 16 + gid;
#pragma unroll
        for (int ni = 0; ni < 4; ni++) {
            const int n = nTile + n0 + ni * 8 + tig * 2;
            const float2 bv = *(const float2*)&g_bias[n];
            float2 o0 = make_float2(acc[mi][ni][0] + bv.x, acc[mi][ni][1] + bv.y);
            float2 o1 = make_float2(acc[mi][ni][2] + bv.x, acc[mi][ni][3] + bv.y);
            *(float2*)&g_G[(size_t)m * GNF + n]       = o0;
            *(float2*)&g_G[(size_t)(m + 8) * GNF + n] = o1;
        }
    }
}

// ---------------- persistent recurrence (R12 winner, unchanged) --------------
#define ST_A (64 * SROW2)
#define ST_B (64 * SROW2)
#define STG  (ST_A + ST_B)
#define NST 6
#define R12_SMEM (NST * STG)
#define NPAIR 12
#define SRBUF (64 * 68 * 4)
#define SROFF (4 * STG)

__global__ __launch_bounds__(256, 2)
void lstm_persistent(const int* __restrict__ x_len)
{
    extern __shared__ __align__(16) char sm[];
    const uint32_t sbase = smem_u32(sm);

    const int tid  = threadIdx.x;
    const int wid  = tid >> 5;
    const int lane = tid & 31;
    const int nTile = blockIdx.x * 64;
    const int b0    = blockIdx.y * 64;
    const int dir   = blockIdx.z;
    const int grp   = dir * 4 + blockIdx.y;

    const __nv_bfloat16* __restrict__ Wd = g_Whh[dir];
    float* __restrict__ outp = g_outd[dir];

    const int ksg = wid >> 2;
    const int w4  = wid & 3;
    const int m0  = (w4 & 1) * 32;
    const int n0  = (w4 >> 1) * 32;

    const int c0r = tid >> 3;
    const int c1r = (tid + 256) >> 3;
    const int c8  = (tid & 7);
    const uint32_t off0 = (uint32_t)(c0r * SROW2 + c8 * 16);
    const uint32_t off1 = (uint32_t)(c1r * SROW2 + c8 * 16);

    const int r8 = lane & 7;
    const int tI = lane >> 3;
    const uint32_t aLaneOff = (uint32_t)((r8 + (tI & 1) * 8) * SROW2 + (tI >> 1) * 16);
    const uint32_t bLaneOff = (uint32_t)((r8 + (tI >> 1) * 8) * SROW2 + (tI & 1) * 16);
    const int gid = lane >> 2;
    const int tig = lane & 3;
    const int jBase = nTile >> 2;

    float* __restrict__ sR0 = (float*)(sm + SROFF);
    float* __restrict__ sR1 = (float*)(sm + SROFF + SRBUF);
    float* __restrict__ sRme = ksg ? sR1 : sR0;

    float hreg[4] = {0.f, 0.f, 0.f, 0.f};
    float creg[4] = {0.f, 0.f, 0.f, 0.f};

    auto issue_B = [&](int kt) {
        const int stage = kt % NST;
        const int seg  = kt >> 3;
        const int ktk  = kt & 7;
        const int bcol = (seg == 2) ? (512 + ktk * 64) : (ktk * 64);
        const uint32_t sb = sbase + stage * STG + ST_A;
        CPA16(sb + off0, Wd + (size_t)(nTile + c0r) * 1024 + bcol + c8 * 8);
        CPA16(sb + off1, Wd + (size_t)(nTile + c1r) * 1024 + bcol + c8 * 8);
    };

    issue_B(0); issue_B(1); issue_B(2); issue_B(3); CPA_COMMIT();

    for (int t = 0; t < LL; t++) {
        const int p2 = t & 1;
        const __nv_bfloat16* __restrict__ hhi = g_hhi[dir][p2];
        const __nv_bfloat16* __restrict__ hlo = g_hlo[dir][p2];
        __nv_bfloat16* __restrict__ hhin = g_hhi[dir][p2 ^ 1];
        __nv_bfloat16* __restrict__ hlon = g_hlo[dir][p2 ^ 1];

        auto issue_A = [&](int kt) {
            const int stage = kt % NST;
            const int seg  = kt >> 3;
            const int acol = (kt & 7) * 64;
            const __nv_bfloat16* __restrict__ hsrc = (seg == 1) ? hlo : hhi;
            const uint32_t sa = sbase + stage * STG;
            CPA16(sa + off0, hsrc + (size_t)(b0 + c0r) * HH + acol + c8 * 8);
            CPA16(sa + off1, hsrc + (size_t)(b0 + c1r) * HH + acol + c8 * 8);
        };
        auto issue_AB = [&](int kt) { issue_A(kt); issue_B(kt); };

        float4 gp[4];
#pragma unroll
        for (int it = 0; it < 4; it++) {
            const int idx = it * 256 + tid;
            const int bl = idx >> 4;
            const int jj = idx & 15;
            const int b  = b0 + bl;
            const int len = x_len[b];
            int tq = t;
            if (dir) { tq = len - 1 - t; if (tq < 0) tq = 0; }
            gp[it] = *(const float4*)(
                g_G + ((size_t)tq * BB + b) * GNF + dir * G4H + (size_t)(jBase + jj) * 4);
        }

        float acc[2][4][4];
#pragma unroll
        for (int i = 0; i < 2; i++)
#pragma unroll
            for (int j = 0; j < 4; j++)
#pragma unroll
                for (int q = 0; q < 4; q++) acc[i][j][q] = 0.f;

        issue_A(0); issue_A(1); CPA_COMMIT();
        issue_A(2); issue_A(3); CPA_COMMIT();

        for (int p = 0; p < NPAIR; p++) {
            asm volatile("cp.async.wait_group 1;" ::: "memory");
            __syncthreads();

            const int kt = 2 * p + ksg;
            const uint32_t sa = sbase + (kt % NST) * STG;
            const uint32_t sb = sa + ST_A;
#pragma unroll
            for (int kk = 0; kk < 4; kk++) {
                uint32_t afr[2][4], bfr[2][4];
#pragma unroll
                for (int mi = 0; mi < 2; mi++)
                    ldmatrix_x4(afr[mi],
                                sa + (uint32_t)((m0 + mi * 16) * SROW2 + kk * 32) + aLaneOff);
#pragma unroll
                for (int nb = 0; nb < 2; nb++)
                    ldmatrix_x4(bfr[nb],
                                sb + (uint32_t)((n0 + nb * 16) * SROW2 + kk * 32) + bLaneOff);
#pragma unroll
                for (int mi = 0; mi < 2; mi++)
#pragma unroll
                    for (int ni = 0; ni < 4; ni++) {
                        const uint32_t* bp = &bfr[ni >> 1][(ni & 1) * 2];
                        mma16816(acc[mi][ni], afr[mi], bp[0], bp[1]);
                    }
            }
            if (p + 2 < NPAIR) { issue_AB(2 * p + 4); issue_AB(2 * p + 5); }
            CPA_COMMIT();
        }
        asm volatile("cp.async.wait_group 0;" ::: "memory");
        __syncthreads();

#pragma unroll
        for (int mi = 0; mi < 2; mi++) {
            const int row = m0 + mi * 16 + gid;
#pragma unroll
            for (int ni = 0; ni < 4; ni++) {
                const int col = n0 + ni * 8 + tig * 2;
                sRme[row * 68 + col]           = acc[mi][ni][0];
                sRme[row * 68 + col + 1]       = acc[mi][ni][1];
                sRme[(row + 8) * 68 + col]     = acc[mi][ni][2];
                sRme[(row + 8) * 68 + col + 1] = acc[mi][ni][3];
            }
        }
        __syncthreads();

#pragma unroll
        for (int it = 0; it < 4; it++) {
            const int idx = it * 256 + tid;
            const int bl = idx >> 4;
            const int jj = idx & 15;
            const int b  = b0 + bl;
            const int j  = jBase + jj;
            const int len = x_len[b];
            const float4 r0 = *(const float4*)&sR0[bl * 68 + jj * 4];
            const float4 r1 = *(const float4*)&sR1[bl * 68 + jj * 4];
            float i_ = fsigmoid(r0.x + r1.x + gp[it].x);
            float f_ = fsigmoid(r0.y + r1.y + gp[it].y);
            float g_ = ftanh(r0.z + r1.z + gp[it].z);
            float o_ = fsigmoid(r0.w + r1.w + gp[it].w);
            float cn = f_ * creg[it] + i_ * g_;
            float hn = o_ * ftanh(cn);
            const bool valid = (t < len);
            if (valid) { creg[it] = cn; hreg[it] = hn; }
            const float ho = hreg[it];
            const size_t hc = (size_t)b * HH + j;
            __nv_bfloat16 hi = __float2bfloat16_rn(ho);
            hhin[hc] = hi;
            hlon[hc] = __float2bfloat16_rn(ho - __bfloat162float(hi));
            outp[((size_t)b * LL + t) * HH + j] = valid ? hn : 0.f;
        }

        if (t + 1 < LL) {
            issue_B(0); issue_B(1); issue_B(2); issue_B(3);
        }
        CPA_COMMIT();

        group_barrier(grp, t);
    }
}

// ---------------- attention + head ------------------------------------------
__global__ __launch_bounds__(256)
void final_kernel(const float* __restrict__ x, const int* __restrict__ x_len,
                  const float* __restrict__ target_word,
                  const float* __restrict__ W_h, const float* __restrict__ b_tanh,
                  const float* __restrict__ W_lin, const float* __restrict__ b_lin,
                  const float* __restrict__ W_out, const float* __restrict__ b_out,
                  float* __restrict__ out)
{
    __shared__ float s_u[LL];
    __shared__ float s_ctx[2 * HH];
    __shared__ float s_lin[512];
    __shared__ float s_red[8];
    __shared__ float s_twdot;

    const int b    = blockIdx.x;
    const int tid  = threadIdx.x;
    const int warp = tid >> 5;
    const int lane = tid & 31;
    const int len  = x_len[b];

    {
        float partial = 0.f;
        for (int d = tid; d < DD; d += 256) {
            float s = 0.f;
#pragma unroll
            for (int k = 0; k < 5; k++)
                s += target_word[((size_t)b * 5 + k) * DD + d];
            partial = fmaf(s * 0.2f, W_h[DD + d], partial);
        }
#pragma unroll
        for (int off = 16; off; off >>= 1)
            partial += __shfl_xor_sync(0xffffffffu, partial, off);
        if (lane == 0) s_red[warp] = partial;
        __syncthreads();
        if (tid == 0) {
            float s = 0.f;
            for (int w = 0; w < 8; w++) s += s_red[w];
            s_twdot = s;
        }
        __syncthreads();
    }
    const float twdot = s_twdot;

    for (int i = 0; i < 16; i++) {
        const int t = warp * 16 + i;
        const float* xe = x + ((size_t)b * LL + t) * DD;
        float a = 0.f;
#pragma unroll 8
        for (int q = 0; q < 32; q++) {
            int d = lane + q * 32;
            a = fmaf(xe[d], W_h[d], a);
        }
#pragma unroll
        for (int off = 16; off; off >>= 1)
            a += __shfl_xor_sync(0xffffffffu, a, off);
        if (lane == 0)
            s_u[t] = (t < len) ? (a + twdot + b_tanh[t]) : -1e6f;
    }
    __syncthreads();

    if (warp == 0) {
        float v[4];
#pragma unroll
        for (int q = 0; q < 4; q++) v[q] = s_u[lane + q * 32];
        float m = fmaxf(fmaxf(v[0], v[1]), fmaxf(v[2], v[3]));
#pragma unroll
        for (int off = 16; off; off >>= 1)
            m = fmaxf(m, __shfl_xor_sync(0xffffffffu, m, off));
        float e[4], s = 0.f;
#pragma unroll
        for (int q = 0; q < 4; q++) { e[q] = expf(v[q] - m); s += e[q]; }
#pragma unroll
        for (int off = 16; off; off >>= 1)
            s += __shfl_xor_sync(0xffffffffu, s, off);
        float inv = 1.f / s;
#pragma unroll
        for (int q = 0; q < 4; q++) s_u[lane + q * 32] = e[q] * inv;
    }
    __syncthreads();

    {
        float accj[4] = {0.f, 0.f, 0.f, 0.f};
        const float* outf = g_outd[0] + (size_t)b * LL * HH;
        const float* outb = g_outd[1] + (size_t)b * LL * HH;
        for (int t = 0; t < LL; t++) {
            const float a = s_u[t];
            int t2 = len - 1 - t;
            if (t2 < 0) t2 = 0;
#pragma unroll
            for (int q = 0; q < 4; q++) {
                const int j = tid + q * 256;
                float hv;
                if (j < HH) hv = outf[(size_t)t * HH + j];
                else        hv = outb[(size_t)t2 * HH + (j - HH)];
                accj[q] = fmaf(a, hv, accj[q]);
            }
        }
#pragma unroll
        for (int q = 0; q < 4; q++) s_ctx[tid + q * 256] = accj[q];
    }
    __syncthreads();

    for (int i = 0; i < 64; i++) {
        const int o = warp * 64 + i;
        const float* wr = W_lin + (size_t)o * (2 * HH);
        float a = 0.f;
#pragma unroll 8
        for (int q = 0; q < 32; q++) {
            int d = lane + q * 32;
            a = fmaf(s_ctx[d], wr[d], a);
        }
#pragma unroll
        for (int off = 16; off; off >>= 1)
            a += __shfl_xor_sync(0xffffffffu, a, off);
        if (lane == 0) s_lin[o] = fmaxf(a + b_lin[o], 0.f);
    }
    __syncthreads();

    if (warp == 0) {
#pragma unroll
        for (int o = 0; o < 3; o++) {
            const float* wr = W_out + (size_t)o * 512;
            float a = 0.f;
#pragma unroll
            for (int q = 0; q < 16; q++) {
                int d = lane + q * 32;
                a = fmaf(s_lin[d], wr[d], a);
            }
#pragma unroll
            for (int off = 16; off; off >>= 1)
                a += __shfl_xor_sync(0xffffffffu, a, off);
            if (lane == 0) out[b * 3 + o] = a + b_out[o];
        }
    }
}

// ---------------- launch -----------------------------------------------------
extern "C" void kernel_launch(void* const* d_in, const int* in_sizes, int n_in,
                              void* d_out, int out_size)
{
    const float* x           = (const float*)d_in[0];
    const int*   x_len       = (const int*)d_in[1];
    const float* target_word = (const float*)d_in[3];
    const float* W_ih_f      = (const float*)d_in[5];
    const float* W_hh_f      = (const float*)d_in[6];
    const float* b_f         = (const float*)d_in[7];
    const float* W_ih_b      = (const float*)d_in[8];
    const float* W_hh_b      = (const float*)d_in[9];
    const float* b_b         = (const float*)d_in[10];
    const float* W_h         = (const float*)d_in[11];
    const float* b_tanh      = (const float*)d_in[12];
    const float* W_lin       = (const float*)d_in[13];
    const float* b_lin       = (const float*)d_in[14];
    const float* W_out       = (const float*)d_in[15];
    const float* b_out       = (const float*)d_in[16];
    float* out = (float*)d_out;

    static bool attr_set = false;
    if (!attr_set) {
        cudaFuncSetAttribute(lstm_persistent,
                             cudaFuncAttributeMaxDynamicSharedMemorySize, R12_SMEM);
        cudaFuncSetAttribute(gemm_mma_kernel,
                             cudaFuncAttributeMaxDynamicSharedMemorySize, G_SMEM);
        attr_set = true;
    }

    init_hc_kernel<<<(BB * HH + 255) / 256, 256>>>();
    convert_x_kernel<<<BB * LL, 256>>>(x);
    convert_w_kernel<<<GNF, 256>>>(W_ih_f, W_ih_b, b_f, b_b);
    {
        dim3 wgrid(G4H, 2);
        convert_whh_kernel<<<wgrid, 128>>>(W_hh_f, W_hh_b);
    }

    dim3 ggrid(GNF / 256, MM_TOT / 128);   // (16, 256) = 4096 blocks
    gemm_mma_kernel<<<ggrid, 512, G_SMEM>>>();

    dim3 sgrid(G4H / 64, BB / 64, 2);      // (32, 4, 2) = 256 persistent blocks
    lstm_persistent<<<sgrid, 256, R12_SMEM>>>(x_len);

    final_kernel<<<BB, 256>>>(x, x_len, target_word, W_h, b_tanh,
                              W_lin, b_lin, W_out, b_out, out);
}